// round 1
// baseline (speedup 1.0000x reference)
#include <cuda_runtime.h>
#include <math.h>

#define BATCH 8
#define TLEN 512
#define NLEN 1024
#define DIM 1024
#define HEADS 16
#define HDIM 64

// Scratch (no cudaMalloc allowed): 32 + 16 + 32 + 16 = 96 MB
__device__ float g_feats[BATCH * NLEN * DIM];
__device__ float g_Qbuf [BATCH * TLEN * DIM];
__device__ float g_Kbuf [BATCH * NLEN * DIM];
__device__ float g_Abuf [BATCH * TLEN * DIM];

// ---------------------------------------------------------------------------
// RMSNorm over rows of DIM=1024. One block (256 threads) per row, float4.
// Safe in-place: each thread reads its own float4 into regs before writing.
// ---------------------------------------------------------------------------
__global__ void rmsnorm_kernel(const float* __restrict__ in,
                               const float* __restrict__ g,
                               float* __restrict__ out) {
    int row = blockIdx.x;
    int tid = threadIdx.x;
    const float4* x4 = (const float4*)(in + (size_t)row * DIM);
    float4 v = x4[tid];
    float s = v.x * v.x + v.y * v.y + v.z * v.z + v.w * v.w;
    #pragma unroll
    for (int o = 16; o > 0; o >>= 1) s += __shfl_xor_sync(0xffffffffu, s, o);

    __shared__ float ws[8];
    __shared__ float rsh;
    if ((tid & 31) == 0) ws[tid >> 5] = s;
    __syncthreads();
    if (tid == 0) {
        float t = 0.f;
        #pragma unroll
        for (int i = 0; i < 8; i++) t += ws[i];
        rsh = rsqrtf(t * (1.0f / DIM) + 1e-6f);
    }
    __syncthreads();
    float r = rsh;
    float4 gv = ((const float4*)g)[tid];
    float4 ov = make_float4(v.x * r * gv.x, v.y * r * gv.y,
                            v.z * r * gv.z, v.w * r * gv.w);
    ((float4*)(out + (size_t)row * DIM))[tid] = ov;
}

// ---------------------------------------------------------------------------
// C[M,1024] = A[M,1024] @ W[1024,1024]^T + bias
// 128x128 block tile, kt=16, 256 threads, 8x8 per thread.
// ---------------------------------------------------------------------------
__global__ __launch_bounds__(256, 2)
void gemm_bias_kernel(const float* __restrict__ A,
                      const float* __restrict__ W,
                      const float* __restrict__ bias,
                      float* __restrict__ C) {
    __shared__ float As[16][132];
    __shared__ float Bs[16][132];

    int tid = threadIdx.x;
    int bm = blockIdx.y * 128;
    int bn = blockIdx.x * 128;
    int tx = tid & 15;          // 0..15  -> n direction
    int ty = tid >> 4;          // 0..15  -> m direction
    int lr = tid >> 2;          // 0..63  load row
    int lc = (tid & 3) << 2;    // 0,4,8,12 load col

    float acc[8][8];
    #pragma unroll
    for (int i = 0; i < 8; i++)
        #pragma unroll
        for (int j = 0; j < 8; j++) acc[i][j] = 0.f;

    for (int k0 = 0; k0 < DIM; k0 += 16) {
        #pragma unroll
        for (int hh = 0; hh < 2; hh++) {
            int row = lr + hh * 64;
            float4 av = *(const float4*)&A[(size_t)(bm + row) * DIM + k0 + lc];
            As[lc + 0][row] = av.x; As[lc + 1][row] = av.y;
            As[lc + 2][row] = av.z; As[lc + 3][row] = av.w;
            float4 wv = *(const float4*)&W[(size_t)(bn + row) * DIM + k0 + lc];
            Bs[lc + 0][row] = wv.x; Bs[lc + 1][row] = wv.y;
            Bs[lc + 2][row] = wv.z; Bs[lc + 3][row] = wv.w;
        }
        __syncthreads();
        #pragma unroll
        for (int k = 0; k < 16; k++) {
            float a[8], b[8];
            *(float4*)&a[0] = *(const float4*)&As[k][ty * 8];
            *(float4*)&a[4] = *(const float4*)&As[k][ty * 8 + 4];
            *(float4*)&b[0] = *(const float4*)&Bs[k][tx * 8];
            *(float4*)&b[4] = *(const float4*)&Bs[k][tx * 8 + 4];
            #pragma unroll
            for (int i = 0; i < 8; i++)
                #pragma unroll
                for (int j = 0; j < 8; j++)
                    acc[i][j] += a[i] * b[j];
        }
        __syncthreads();
    }

    float4 bi0 = *(const float4*)&bias[bn + tx * 8];
    float4 bi1 = *(const float4*)&bias[bn + tx * 8 + 4];
    #pragma unroll
    for (int i = 0; i < 8; i++) {
        size_t row = (size_t)(bm + ty * 8 + i);
        float4 o0 = make_float4(acc[i][0] + bi0.x, acc[i][1] + bi0.y,
                                acc[i][2] + bi0.z, acc[i][3] + bi0.w);
        float4 o1 = make_float4(acc[i][4] + bi1.x, acc[i][5] + bi1.y,
                                acc[i][6] + bi1.z, acc[i][7] + bi1.w);
        *(float4*)&C[row * DIM + bn + tx * 8]     = o0;
        *(float4*)&C[row * DIM + bn + tx * 8 + 4] = o1;
    }
}

// ---------------------------------------------------------------------------
// Flash attention: grid (B*H, T/16), 256 threads (8 warps), warp owns 2 rows.
// K/V chunks of 32 n-rows staged in smem; online softmax; lane j scores n0+j;
// each lane accumulates output dims (2*lane, 2*lane+1).
// ---------------------------------------------------------------------------
__global__ __launch_bounds__(256)
void attn_kernel(const float* __restrict__ Q, const float* __restrict__ K,
                 const float* __restrict__ V, float* __restrict__ O) {
    __shared__ float Ks[32][68];
    __shared__ float Vs[32][68];
    __shared__ float qs[16][68];

    int b  = blockIdx.x >> 4;
    int h  = blockIdx.x & 15;
    int t0 = blockIdx.y * 16;
    int tid  = threadIdx.x;
    int warp = tid >> 5, lane = tid & 31;

    // Load Q tile (scaled by 1/sqrt(64))
    for (int i = tid; i < 16 * HDIM; i += 256) {
        int r = i >> 6, d = i & 63;
        qs[r][d] = Q[((size_t)(b * TLEN + t0 + r)) * DIM + h * HDIM + d] * 0.125f;
    }
    __syncthreads();

    int r0 = warp * 2, r1 = warp * 2 + 1;
    float m0 = -INFINITY, m1 = -INFINITY;
    float l0 = 0.f, l1 = 0.f;
    float2 acc0 = make_float2(0.f, 0.f);
    float2 acc1 = make_float2(0.f, 0.f);

    for (int n0 = 0; n0 < NLEN; n0 += 32) {
        for (int i = tid; i < 32 * HDIM; i += 256) {
            int r = i >> 6, d = i & 63;
            size_t gb = ((size_t)(b * NLEN + n0 + r)) * DIM + h * HDIM + d;
            Ks[r][d] = K[gb];
            Vs[r][d] = V[gb];
        }
        __syncthreads();

        // scores for n = n0 + lane
        float s0 = 0.f, s1 = 0.f;
        const float4* krow = (const float4*)&Ks[lane][0];
        const float4* q0r  = (const float4*)&qs[r0][0];
        const float4* q1r  = (const float4*)&qs[r1][0];
        #pragma unroll
        for (int d4 = 0; d4 < 16; d4++) {
            float4 kv = krow[d4];
            float4 qa = q0r[d4];
            float4 qb = q1r[d4];
            s0 += qa.x * kv.x + qa.y * kv.y + qa.z * kv.z + qa.w * kv.w;
            s1 += qb.x * kv.x + qb.y * kv.y + qb.z * kv.z + qb.w * kv.w;
        }

        // chunk max (all lanes end with same value)
        float cm0 = s0, cm1 = s1;
        #pragma unroll
        for (int o = 16; o > 0; o >>= 1) {
            cm0 = fmaxf(cm0, __shfl_xor_sync(0xffffffffu, cm0, o));
            cm1 = fmaxf(cm1, __shfl_xor_sync(0xffffffffu, cm1, o));
        }
        float mn0 = fmaxf(m0, cm0), mn1 = fmaxf(m1, cm1);
        float sc0 = __expf(m0 - mn0), sc1 = __expf(m1 - mn1);
        float p0  = __expf(s0 - mn0), p1  = __expf(s1 - mn1);
        l0 = l0 * sc0 + p0;
        l1 = l1 * sc1 + p1;
        acc0.x *= sc0; acc0.y *= sc0;
        acc1.x *= sc1; acc1.y *= sc1;
        m0 = mn0; m1 = mn1;

        #pragma unroll
        for (int jj = 0; jj < 32; jj++) {
            float pa = __shfl_sync(0xffffffffu, p0, jj);
            float pb = __shfl_sync(0xffffffffu, p1, jj);
            float2 vv = *(const float2*)&Vs[jj][lane * 2];
            acc0.x += pa * vv.x; acc0.y += pa * vv.y;
            acc1.x += pb * vv.x; acc1.y += pb * vv.y;
        }
        __syncthreads();
    }

    // total denominator across lanes
    #pragma unroll
    for (int o = 16; o > 0; o >>= 1) {
        l0 += __shfl_xor_sync(0xffffffffu, l0, o);
        l1 += __shfl_xor_sync(0xffffffffu, l1, o);
    }
    float inv0 = 1.f / l0, inv1 = 1.f / l1;
    size_t ob0 = ((size_t)(b * TLEN + t0 + r0)) * DIM + h * HDIM + lane * 2;
    size_t ob1 = ((size_t)(b * TLEN + t0 + r1)) * DIM + h * HDIM + lane * 2;
    *(float2*)&O[ob0] = make_float2(acc0.x * inv0, acc0.y * inv0);
    *(float2*)&O[ob1] = make_float2(acc1.x * inv1, acc1.y * inv1);
}

// ---------------------------------------------------------------------------
extern "C" void kernel_launch(void* const* d_in, const int* in_sizes, int n_in,
                              void* d_out, int out_size) {
    const float* text     = (const float*)d_in[0];
    const float* features = (const float*)d_in[1];
    const float* W_q      = (const float*)d_in[2];
    const float* b_q      = (const float*)d_in[3];
    const float* W_k      = (const float*)d_in[4];
    const float* b_k      = (const float*)d_in[5];
    const float* W_o      = (const float*)d_in[6];
    const float* b_o      = (const float*)d_in[7];
    const float* g_feat   = (const float*)d_in[8];
    const float* g_q      = (const float*)d_in[9];
    const float* g_k      = (const float*)d_in[10];
    float* out = (float*)d_out;

    float *feats, *Qb, *Kb, *Ab;
    cudaGetSymbolAddress((void**)&feats, g_feats);
    cudaGetSymbolAddress((void**)&Qb,    g_Qbuf);
    cudaGetSymbolAddress((void**)&Kb,    g_Kbuf);
    cudaGetSymbolAddress((void**)&Ab,    g_Abuf);

    // 1. feats = rmsnorm(features, g_feat)
    rmsnorm_kernel<<<BATCH * NLEN, 256>>>(features, g_feat, feats);

    // 2. Q = rmsnorm(text @ Wq^T + bq, g_q)    [4096 x 1024]
    gemm_bias_kernel<<<dim3(DIM / 128, (BATCH * TLEN) / 128), 256>>>(text, W_q, b_q, Qb);
    rmsnorm_kernel<<<BATCH * TLEN, 256>>>(Qb, g_q, Qb);

    // 3. K = rmsnorm(feats @ Wk^T + bk, g_k)   [8192 x 1024]
    gemm_bias_kernel<<<dim3(DIM / 128, (BATCH * NLEN) / 128), 256>>>(feats, W_k, b_k, Kb);
    rmsnorm_kernel<<<BATCH * NLEN, 256>>>(Kb, g_k, Kb);

    // 4. attention: softmax(Q Kh^T / 8) @ Vh   -> Ab [4096 x 1024]
    attn_kernel<<<dim3(BATCH * HEADS, TLEN / 16), 256>>>(Qb, Kb, feats, Ab);

    // 5. out = Ab @ Wo^T + bo
    gemm_bias_kernel<<<dim3(DIM / 128, (BATCH * TLEN) / 128), 256>>>(Ab, W_o, b_o, out);
}

// round 2
// speedup vs baseline: 1.3171x; 1.3171x over previous
#include <cuda_runtime.h>
#include <math.h>

#define BATCH 8
#define TLEN 512
#define NLEN 1024
#define DIM 1024
#define HEADS 16
#define HDIM 64

// Scratch (no cudaMalloc allowed)
__device__ float g_feats[BATCH * NLEN * DIM];
__device__ float g_Qbuf [BATCH * TLEN * DIM];
__device__ float g_Kbuf [BATCH * NLEN * DIM];
__device__ float g_Abuf [BATCH * TLEN * DIM];

// ---------------------------------------------------------------------------
// RMSNorm over rows of DIM=1024. One block (256 threads) per row, float4.
// ---------------------------------------------------------------------------
__global__ void rmsnorm_kernel(const float* __restrict__ in,
                               const float* __restrict__ g,
                               float* __restrict__ out) {
    int row = blockIdx.x;
    int tid = threadIdx.x;
    const float4* x4 = (const float4*)(in + (size_t)row * DIM);
    float4 v = x4[tid];
    float s = v.x * v.x + v.y * v.y + v.z * v.z + v.w * v.w;
    #pragma unroll
    for (int o = 16; o > 0; o >>= 1) s += __shfl_xor_sync(0xffffffffu, s, o);

    __shared__ float ws[8];
    __shared__ float rsh;
    if ((tid & 31) == 0) ws[tid >> 5] = s;
    __syncthreads();
    if (tid == 0) {
        float t = 0.f;
        #pragma unroll
        for (int i = 0; i < 8; i++) t += ws[i];
        rsh = rsqrtf(t * (1.0f / DIM) + 1e-6f);
    }
    __syncthreads();
    float r = rsh;
    float4 gv = ((const float4*)g)[tid];
    float4 ov = make_float4(v.x * r * gv.x, v.y * r * gv.y,
                            v.z * r * gv.z, v.w * r * gv.w);
    ((float4*)(out + (size_t)row * DIM))[tid] = ov;
}

// ---------------------------------------------------------------------------
// C[M,1024] = A[M,1024] @ W[1024,1024]^T + bias
// 128x128 block tile, kt=8, double-buffered smem, 256 threads, 8x8/thread.
// ---------------------------------------------------------------------------
__global__ __launch_bounds__(256, 2)
void gemm_bias_kernel(const float* __restrict__ A,
                      const float* __restrict__ W,
                      const float* __restrict__ bias,
                      float* __restrict__ C) {
    __shared__ float As[2][8][132];
    __shared__ float Bs[2][8][132];

    int tid = threadIdx.x;
    int bm = blockIdx.y * 128;
    int bn = blockIdx.x * 128;
    int tx = tid & 15;          // n direction
    int ty = tid >> 4;          // m direction
    int lr = tid >> 1;          // 0..127 load row
    int lc = (tid & 1) << 2;    // 0 or 4

    const float* Aptr = &A[(size_t)(bm + lr) * DIM + lc];
    const float* Wptr = &W[(size_t)(bn + lr) * DIM + lc];

    float acc[8][8];
    #pragma unroll
    for (int i = 0; i < 8; i++)
        #pragma unroll
        for (int j = 0; j < 8; j++) acc[i][j] = 0.f;

    float4 ra = *(const float4*)Aptr;
    float4 rw = *(const float4*)Wptr;
    As[0][lc + 0][lr] = ra.x; As[0][lc + 1][lr] = ra.y;
    As[0][lc + 2][lr] = ra.z; As[0][lc + 3][lr] = ra.w;
    Bs[0][lc + 0][lr] = rw.x; Bs[0][lc + 1][lr] = rw.y;
    Bs[0][lc + 2][lr] = rw.z; Bs[0][lc + 3][lr] = rw.w;
    __syncthreads();

    int buf = 0;
    for (int k0 = 0; k0 < DIM; k0 += 8) {
        if (k0 + 8 < DIM) {
            ra = *(const float4*)(Aptr + k0 + 8);
            rw = *(const float4*)(Wptr + k0 + 8);
        }
        #pragma unroll
        for (int k = 0; k < 8; k++) {
            float a[8], b[8];
            *(float4*)&a[0] = *(const float4*)&As[buf][k][ty * 8];
            *(float4*)&a[4] = *(const float4*)&As[buf][k][ty * 8 + 4];
            *(float4*)&b[0] = *(const float4*)&Bs[buf][k][tx * 8];
            *(float4*)&b[4] = *(const float4*)&Bs[buf][k][tx * 8 + 4];
            #pragma unroll
            for (int i = 0; i < 8; i++)
                #pragma unroll
                for (int j = 0; j < 8; j++)
                    acc[i][j] += a[i] * b[j];
        }
        if (k0 + 8 < DIM) {
            int nb = buf ^ 1;
            As[nb][lc + 0][lr] = ra.x; As[nb][lc + 1][lr] = ra.y;
            As[nb][lc + 2][lr] = ra.z; As[nb][lc + 3][lr] = ra.w;
            Bs[nb][lc + 0][lr] = rw.x; Bs[nb][lc + 1][lr] = rw.y;
            Bs[nb][lc + 2][lr] = rw.z; Bs[nb][lc + 3][lr] = rw.w;
        }
        buf ^= 1;
        __syncthreads();
    }

    float4 bi0 = *(const float4*)&bias[bn + tx * 8];
    float4 bi1 = *(const float4*)&bias[bn + tx * 8 + 4];
    #pragma unroll
    for (int i = 0; i < 8; i++) {
        size_t row = (size_t)(bm + ty * 8 + i);
        float4 o0 = make_float4(acc[i][0] + bi0.x, acc[i][1] + bi0.y,
                                acc[i][2] + bi0.z, acc[i][3] + bi0.w);
        float4 o1 = make_float4(acc[i][4] + bi1.x, acc[i][5] + bi1.y,
                                acc[i][6] + bi1.z, acc[i][7] + bi1.w);
        *(float4*)&C[row * DIM + bn + tx * 8]     = o0;
        *(float4*)&C[row * DIM + bn + tx * 8 + 4] = o1;
    }
}

// ---------------------------------------------------------------------------
// Flash attention, GEMM-style register tiling.
// Block: 64 t-rows x one head. 256 threads, 4x4 tile per thread.
// Per 64-n chunk: S = Q@K^T (smem, d-major), online softmax, P->smem, P@V.
// Dynamic smem: Qt[64][68] + Kt[64][68] + Vs[64][68] + Ps[64][68] = 69632 B.
// ---------------------------------------------------------------------------
#define APAD 68
__global__ __launch_bounds__(256)
void attn_kernel(const float* __restrict__ Q, const float* __restrict__ K,
                 const float* __restrict__ V, float* __restrict__ O) {
    extern __shared__ float sm[];
    float* Qt = sm;                 // Qt[d*APAD + t]
    float* Kt = sm + 64 * APAD;     // Kt[d*APAD + n]
    float* Vs = Kt + 64 * APAD;     // Vs[n*APAD + d]
    float* Ps = Vs + 64 * APAD;     // Ps[n*APAD + t]

    int b  = blockIdx.x >> 4;
    int h  = blockIdx.x & 15;
    int t0 = blockIdx.y * 64;
    int tid = threadIdx.x;
    int tx = tid & 15;   // n/d-out direction
    int ty = tid >> 4;   // t direction

    // Load Q tile transposed (d-major), pre-scaled by 1/sqrt(64)
    for (int i = tid; i < 1024; i += 256) {
        int t = i >> 4, d = (i & 15) << 2;
        float4 q = *(const float4*)&Q[((size_t)(b * TLEN + t0 + t)) * DIM + h * HDIM + d];
        Qt[(d + 0) * APAD + t] = q.x * 0.125f;
        Qt[(d + 1) * APAD + t] = q.y * 0.125f;
        Qt[(d + 2) * APAD + t] = q.z * 0.125f;
        Qt[(d + 3) * APAD + t] = q.w * 0.125f;
    }

    float o[4][4];
    float m[4], l[4];
    #pragma unroll
    for (int i = 0; i < 4; i++) {
        m[i] = -INFINITY; l[i] = 0.f;
        #pragma unroll
        for (int j = 0; j < 4; j++) o[i][j] = 0.f;
    }

    for (int n0 = 0; n0 < NLEN; n0 += 64) {
        __syncthreads();   // Vs/Kt free; also guards Qt on first iter
        for (int i = tid; i < 1024; i += 256) {
            int n = i >> 4, d = (i & 15) << 2;
            size_t gb = ((size_t)(b * NLEN + n0 + n)) * DIM + h * HDIM + d;
            float4 kv = *(const float4*)&K[gb];
            Kt[(d + 0) * APAD + n] = kv.x;
            Kt[(d + 1) * APAD + n] = kv.y;
            Kt[(d + 2) * APAD + n] = kv.z;
            Kt[(d + 3) * APAD + n] = kv.w;
            float4 vv = *(const float4*)&V[gb];
            *(float4*)&Vs[n * APAD + d] = vv;
        }
        __syncthreads();

        // S tile: s[i][j] = sum_d Q[t][d] * K[n][d]
        float s[4][4];
        #pragma unroll
        for (int i = 0; i < 4; i++)
            #pragma unroll
            for (int j = 0; j < 4; j++) s[i][j] = 0.f;
        #pragma unroll 8
        for (int d = 0; d < 64; d++) {
            float a[4], bb[4];
            *(float4*)a  = *(const float4*)&Qt[d * APAD + ty * 4];
            *(float4*)bb = *(const float4*)&Kt[d * APAD + tx * 4];
            #pragma unroll
            for (int i = 0; i < 4; i++)
                #pragma unroll
                for (int j = 0; j < 4; j++)
                    s[i][j] += a[i] * bb[j];
        }

        // Online softmax (row reductions across 16 lanes sharing ty)
        #pragma unroll
        for (int i = 0; i < 4; i++) {
            float cm = fmaxf(fmaxf(s[i][0], s[i][1]), fmaxf(s[i][2], s[i][3]));
            cm = fmaxf(cm, __shfl_xor_sync(0xffffffffu, cm, 1));
            cm = fmaxf(cm, __shfl_xor_sync(0xffffffffu, cm, 2));
            cm = fmaxf(cm, __shfl_xor_sync(0xffffffffu, cm, 4));
            cm = fmaxf(cm, __shfl_xor_sync(0xffffffffu, cm, 8));
            float mn = fmaxf(m[i], cm);
            float sc = __expf(m[i] - mn);
            m[i] = mn;
            float rs = 0.f;
            #pragma unroll
            for (int j = 0; j < 4; j++) {
                s[i][j] = __expf(s[i][j] - mn);
                rs += s[i][j];
            }
            rs += __shfl_xor_sync(0xffffffffu, rs, 1);
            rs += __shfl_xor_sync(0xffffffffu, rs, 2);
            rs += __shfl_xor_sync(0xffffffffu, rs, 4);
            rs += __shfl_xor_sync(0xffffffffu, rs, 8);
            l[i] = l[i] * sc + rs;
            #pragma unroll
            for (int j = 0; j < 4; j++) o[i][j] *= sc;
        }

        // Stage P transposed: Ps[n][t]
        #pragma unroll
        for (int j = 0; j < 4; j++) {
            float4 pv = make_float4(s[0][j], s[1][j], s[2][j], s[3][j]);
            *(float4*)&Ps[(tx * 4 + j) * APAD + ty * 4] = pv;
        }
        __syncthreads();

        // O += P @ V
        #pragma unroll 8
        for (int n = 0; n < 64; n++) {
            float a[4], bb[4];
            *(float4*)a  = *(const float4*)&Ps[n * APAD + ty * 4];
            *(float4*)bb = *(const float4*)&Vs[n * APAD + tx * 4];
            #pragma unroll
            for (int i = 0; i < 4; i++)
                #pragma unroll
                for (int j = 0; j < 4; j++)
                    o[i][j] += a[i] * bb[j];
        }
    }

    #pragma unroll
    for (int i = 0; i < 4; i++) {
        float inv = 1.f / l[i];
        float4 ov = make_float4(o[i][0] * inv, o[i][1] * inv,
                                o[i][2] * inv, o[i][3] * inv);
        *(float4*)&O[((size_t)(b * TLEN + t0 + ty * 4 + i)) * DIM + h * HDIM + tx * 4] = ov;
    }
}

// ---------------------------------------------------------------------------
extern "C" void kernel_launch(void* const* d_in, const int* in_sizes, int n_in,
                              void* d_out, int out_size) {
    const float* text     = (const float*)d_in[0];
    const float* features = (const float*)d_in[1];
    const float* W_q      = (const float*)d_in[2];
    const float* b_q      = (const float*)d_in[3];
    const float* W_k      = (const float*)d_in[4];
    const float* b_k      = (const float*)d_in[5];
    const float* W_o      = (const float*)d_in[6];
    const float* b_o      = (const float*)d_in[7];
    const float* g_feat   = (const float*)d_in[8];
    const float* g_q      = (const float*)d_in[9];
    const float* g_k      = (const float*)d_in[10];
    float* out = (float*)d_out;

    float *feats, *Qb, *Kb, *Ab;
    cudaGetSymbolAddress((void**)&feats, g_feats);
    cudaGetSymbolAddress((void**)&Qb,    g_Qbuf);
    cudaGetSymbolAddress((void**)&Kb,    g_Kbuf);
    cudaGetSymbolAddress((void**)&Ab,    g_Abuf);

    static int attn_smem_set = 0;
    const int ATTN_SMEM = 4 * 64 * APAD * sizeof(float);  // 69632
    if (!attn_smem_set) {
        cudaFuncSetAttribute(attn_kernel,
                             cudaFuncAttributeMaxDynamicSharedMemorySize, ATTN_SMEM);
        attn_smem_set = 1;
    }

    // 1. feats = rmsnorm(features, g_feat)
    rmsnorm_kernel<<<BATCH * NLEN, 256>>>(features, g_feat, feats);

    // 2. Q = rmsnorm(text @ Wq^T + bq, g_q)
    gemm_bias_kernel<<<dim3(DIM / 128, (BATCH * TLEN) / 128), 256>>>(text, W_q, b_q, Qb);
    rmsnorm_kernel<<<BATCH * TLEN, 256>>>(Qb, g_q, Qb);

    // 3. K = rmsnorm(feats @ Wk^T + bk, g_k)
    gemm_bias_kernel<<<dim3(DIM / 128, (BATCH * NLEN) / 128), 256>>>(feats, W_k, b_k, Kb);
    rmsnorm_kernel<<<BATCH * NLEN, 256>>>(Kb, g_k, Kb);

    // 4. attention
    attn_kernel<<<dim3(BATCH * HEADS, TLEN / 64), 256, ATTN_SMEM>>>(Qb, Kb, feats, Ab);

    // 5. out = Ab @ Wo^T + bo
    gemm_bias_kernel<<<dim3(DIM / 128, (BATCH * TLEN) / 128), 256>>>(Ab, W_o, b_o, out);
}

// round 3
// speedup vs baseline: 1.3332x; 1.0122x over previous
#include <cuda_runtime.h>
#include <math.h>

#define BATCH 8
#define TLEN 512
#define NLEN 1024
#define DIM 1024
#define HEADS 16
#define HDIM 64

typedef unsigned long long u64;

__device__ __forceinline__ u64 fma2(u64 a, u64 b, u64 c) {
    u64 d;
    asm("fma.rn.f32x2 %0, %1, %2, %3;" : "=l"(d) : "l"(a), "l"(b), "l"(c));
    return d;
}
__device__ __forceinline__ u64 mul2(u64 a, u64 b) {
    u64 d;
    asm("mul.rn.f32x2 %0, %1, %2;" : "=l"(d) : "l"(a), "l"(b));
    return d;
}
__device__ __forceinline__ u64 pack2(float lo, float hi) {
    u64 d;
    asm("mov.b64 %0, {%1, %2};" : "=l"(d) : "f"(lo), "f"(hi));
    return d;
}
__device__ __forceinline__ void unpack2(u64 v, float& lo, float& hi) {
    asm("mov.b64 {%0, %1}, %2;" : "=f"(lo), "=f"(hi) : "l"(v));
}

// Scratch (no cudaMalloc allowed)
__device__ float g_feats[BATCH * NLEN * DIM];
__device__ float g_Qbuf [BATCH * TLEN * DIM];
__device__ float g_Kbuf [BATCH * NLEN * DIM];
__device__ float g_Abuf [BATCH * TLEN * DIM];

// ---------------------------------------------------------------------------
// RMSNorm over rows of DIM=1024. One block (256 threads) per row, float4.
// ---------------------------------------------------------------------------
__global__ void rmsnorm_kernel(const float* __restrict__ in,
                               const float* __restrict__ g,
                               float* __restrict__ out) {
    int row = blockIdx.x;
    int tid = threadIdx.x;
    const float4* x4 = (const float4*)(in + (size_t)row * DIM);
    float4 v = x4[tid];
    float s = v.x * v.x + v.y * v.y + v.z * v.z + v.w * v.w;
    #pragma unroll
    for (int o = 16; o > 0; o >>= 1) s += __shfl_xor_sync(0xffffffffu, s, o);

    __shared__ float ws[8];
    __shared__ float rsh;
    if ((tid & 31) == 0) ws[tid >> 5] = s;
    __syncthreads();
    if (tid == 0) {
        float t = 0.f;
        #pragma unroll
        for (int i = 0; i < 8; i++) t += ws[i];
        rsh = rsqrtf(t * (1.0f / DIM) + 1e-6f);
    }
    __syncthreads();
    float r = rsh;
    float4 gv = ((const float4*)g)[tid];
    float4 ov = make_float4(v.x * r * gv.x, v.y * r * gv.y,
                            v.z * r * gv.z, v.w * r * gv.w);
    ((float4*)(out + (size_t)row * DIM))[tid] = ov;
}

// ---------------------------------------------------------------------------
// C[M,1024] = A[M,1024] @ W[1024,1024]^T + bias
// 128x128 block tile, kt=8, double-buffered, 256 threads, 8x8/thread,
// inner product via packed fma.rn.f32x2 (acc pairs along m).
// ---------------------------------------------------------------------------
__global__ __launch_bounds__(256, 2)
void gemm_bias_kernel(const float* __restrict__ A,
                      const float* __restrict__ W,
                      const float* __restrict__ bias,
                      float* __restrict__ C) {
    __shared__ float As[2][8][132];
    __shared__ float Bs[2][8][132];

    int tid = threadIdx.x;
    int bm = blockIdx.y * 128;
    int bn = blockIdx.x * 128;
    int tx = tid & 15;          // n direction
    int ty = tid >> 4;          // m direction
    int lr = tid >> 1;          // 0..127 load row
    int lc = (tid & 1) << 2;    // 0 or 4

    const float* Aptr = &A[(size_t)(bm + lr) * DIM + lc];
    const float* Wptr = &W[(size_t)(bn + lr) * DIM + lc];

    // acc2[ii][j] = (acc[2ii][j], acc[2ii+1][j])  packed along m
    u64 acc2[4][8];
    #pragma unroll
    for (int ii = 0; ii < 4; ii++)
        #pragma unroll
        for (int j = 0; j < 8; j++) acc2[ii][j] = 0ull;

    float4 ra = *(const float4*)Aptr;
    float4 rw = *(const float4*)Wptr;
    As[0][lc + 0][lr] = ra.x; As[0][lc + 1][lr] = ra.y;
    As[0][lc + 2][lr] = ra.z; As[0][lc + 3][lr] = ra.w;
    Bs[0][lc + 0][lr] = rw.x; Bs[0][lc + 1][lr] = rw.y;
    Bs[0][lc + 2][lr] = rw.z; Bs[0][lc + 3][lr] = rw.w;
    __syncthreads();

    int buf = 0;
    for (int k0 = 0; k0 < DIM; k0 += 8) {
        if (k0 + 8 < DIM) {
            ra = *(const float4*)(Aptr + k0 + 8);
            rw = *(const float4*)(Wptr + k0 + 8);
        }
        #pragma unroll
        for (int k = 0; k < 8; k++) {
            u64 a2[4];
            ulonglong2 av0 = *(const ulonglong2*)&As[buf][k][ty * 8];
            ulonglong2 av1 = *(const ulonglong2*)&As[buf][k][ty * 8 + 4];
            a2[0] = av0.x; a2[1] = av0.y; a2[2] = av1.x; a2[3] = av1.y;
            float b[8];
            *(float4*)&b[0] = *(const float4*)&Bs[buf][k][tx * 8];
            *(float4*)&b[4] = *(const float4*)&Bs[buf][k][tx * 8 + 4];
            #pragma unroll
            for (int j = 0; j < 8; j++) {
                u64 b2 = pack2(b[j], b[j]);
                #pragma unroll
                for (int ii = 0; ii < 4; ii++)
                    acc2[ii][j] = fma2(a2[ii], b2, acc2[ii][j]);
            }
        }
        if (k0 + 8 < DIM) {
            int nb = buf ^ 1;
            As[nb][lc + 0][lr] = ra.x; As[nb][lc + 1][lr] = ra.y;
            As[nb][lc + 2][lr] = ra.z; As[nb][lc + 3][lr] = ra.w;
            Bs[nb][lc + 0][lr] = rw.x; Bs[nb][lc + 1][lr] = rw.y;
            Bs[nb][lc + 2][lr] = rw.z; Bs[nb][lc + 3][lr] = rw.w;
        }
        buf ^= 1;
        __syncthreads();
    }

    float bi[8];
    *(float4*)&bi[0] = *(const float4*)&bias[bn + tx * 8];
    *(float4*)&bi[4] = *(const float4*)&bias[bn + tx * 8 + 4];
    #pragma unroll
    for (int ii = 0; ii < 4; ii++) {
        float lo[8], hi[8];
        #pragma unroll
        for (int j = 0; j < 8; j++) {
            unpack2(acc2[ii][j], lo[j], hi[j]);
            lo[j] += bi[j]; hi[j] += bi[j];
        }
        size_t re = (size_t)(bm + ty * 8 + 2 * ii);
        *(float4*)&C[re * DIM + bn + tx * 8]           = *(float4*)&lo[0];
        *(float4*)&C[re * DIM + bn + tx * 8 + 4]       = *(float4*)&lo[4];
        *(float4*)&C[(re + 1) * DIM + bn + tx * 8]     = *(float4*)&hi[0];
        *(float4*)&C[(re + 1) * DIM + bn + tx * 8 + 4] = *(float4*)&hi[4];
    }
}

// ---------------------------------------------------------------------------
// Flash attention, register tiling + packed f32x2 math.
// Block: 64 t-rows x one head. 256 threads, 4x4 tile per thread (packed 2x4).
// ---------------------------------------------------------------------------
#define APAD 68
__global__ __launch_bounds__(256)
void attn_kernel(const float* __restrict__ Q, const float* __restrict__ K,
                 const float* __restrict__ V, float* __restrict__ O) {
    extern __shared__ float sm[];
    float* Qt = sm;                 // Qt[d*APAD + t]
    float* Kt = sm + 64 * APAD;     // Kt[d*APAD + n]
    float* Vs = Kt + 64 * APAD;     // Vs[n*APAD + d]
    float* Ps = Vs + 64 * APAD;     // Ps[n*APAD + t]

    int b  = blockIdx.x >> 4;
    int h  = blockIdx.x & 15;
    int t0 = blockIdx.y * 64;
    int tid = threadIdx.x;
    int tx = tid & 15;   // n / d-out direction
    int ty = tid >> 4;   // t direction

    // Load Q tile transposed (d-major), pre-scaled by 1/sqrt(64)
    for (int i = tid; i < 1024; i += 256) {
        int t = i >> 4, d = (i & 15) << 2;
        float4 q = *(const float4*)&Q[((size_t)(b * TLEN + t0 + t)) * DIM + h * HDIM + d];
        Qt[(d + 0) * APAD + t] = q.x * 0.125f;
        Qt[(d + 1) * APAD + t] = q.y * 0.125f;
        Qt[(d + 2) * APAD + t] = q.z * 0.125f;
        Qt[(d + 3) * APAD + t] = q.w * 0.125f;
    }

    u64 o2[2][4];          // packed along t: (o[2ii][j], o[2ii+1][j])
    float m[4], l[4];
    #pragma unroll
    for (int i = 0; i < 4; i++) { m[i] = -INFINITY; l[i] = 0.f; }
    #pragma unroll
    for (int ii = 0; ii < 2; ii++)
        #pragma unroll
        for (int j = 0; j < 4; j++) o2[ii][j] = 0ull;

    for (int n0 = 0; n0 < NLEN; n0 += 64) {
        __syncthreads();
        for (int i = tid; i < 1024; i += 256) {
            int n = i >> 4, d = (i & 15) << 2;
            size_t gb = ((size_t)(b * NLEN + n0 + n)) * DIM + h * HDIM + d;
            float4 kv = *(const float4*)&K[gb];
            Kt[(d + 0) * APAD + n] = kv.x;
            Kt[(d + 1) * APAD + n] = kv.y;
            Kt[(d + 2) * APAD + n] = kv.z;
            Kt[(d + 3) * APAD + n] = kv.w;
            float4 vv = *(const float4*)&V[gb];
            *(float4*)&Vs[n * APAD + d] = vv;
        }
        __syncthreads();

        // S tile packed: s2[ii][j] = (s[2ii][j], s[2ii+1][j])
        u64 s2[2][4];
        #pragma unroll
        for (int ii = 0; ii < 2; ii++)
            #pragma unroll
            for (int j = 0; j < 4; j++) s2[ii][j] = 0ull;
        #pragma unroll 8
        for (int d = 0; d < 64; d++) {
            ulonglong2 qa = *(const ulonglong2*)&Qt[d * APAD + ty * 4];
            float4 kv = *(const float4*)&Kt[d * APAD + tx * 4];
            u64 b0 = pack2(kv.x, kv.x), b1 = pack2(kv.y, kv.y);
            u64 b2 = pack2(kv.z, kv.z), b3 = pack2(kv.w, kv.w);
            s2[0][0] = fma2(qa.x, b0, s2[0][0]);
            s2[1][0] = fma2(qa.y, b0, s2[1][0]);
            s2[0][1] = fma2(qa.x, b1, s2[0][1]);
            s2[1][1] = fma2(qa.y, b1, s2[1][1]);
            s2[0][2] = fma2(qa.x, b2, s2[0][2]);
            s2[1][2] = fma2(qa.y, b2, s2[1][2]);
            s2[0][3] = fma2(qa.x, b3, s2[0][3]);
            s2[1][3] = fma2(qa.y, b3, s2[1][3]);
        }

        // Unpack scores for softmax
        float s[4][4];
        #pragma unroll
        for (int ii = 0; ii < 2; ii++)
            #pragma unroll
            for (int j = 0; j < 4; j++)
                unpack2(s2[ii][j], s[2 * ii][j], s[2 * ii + 1][j]);

        float sc[4];
        #pragma unroll
        for (int i = 0; i < 4; i++) {
            float cm = fmaxf(fmaxf(s[i][0], s[i][1]), fmaxf(s[i][2], s[i][3]));
            cm = fmaxf(cm, __shfl_xor_sync(0xffffffffu, cm, 1));
            cm = fmaxf(cm, __shfl_xor_sync(0xffffffffu, cm, 2));
            cm = fmaxf(cm, __shfl_xor_sync(0xffffffffu, cm, 4));
            cm = fmaxf(cm, __shfl_xor_sync(0xffffffffu, cm, 8));
            float mn = fmaxf(m[i], cm);
            sc[i] = __expf(m[i] - mn);
            m[i] = mn;
            float rs = 0.f;
            #pragma unroll
            for (int j = 0; j < 4; j++) {
                s[i][j] = __expf(s[i][j] - mn);
                rs += s[i][j];
            }
            rs += __shfl_xor_sync(0xffffffffu, rs, 1);
            rs += __shfl_xor_sync(0xffffffffu, rs, 2);
            rs += __shfl_xor_sync(0xffffffffu, rs, 4);
            rs += __shfl_xor_sync(0xffffffffu, rs, 8);
            l[i] = l[i] * sc[i] + rs;
        }
        // Rescale packed output accumulators
        #pragma unroll
        for (int ii = 0; ii < 2; ii++) {
            u64 scp = pack2(sc[2 * ii], sc[2 * ii + 1]);
            #pragma unroll
            for (int j = 0; j < 4; j++) o2[ii][j] = mul2(o2[ii][j], scp);
        }

        // Stage P transposed: Ps[n][t]
        #pragma unroll
        for (int j = 0; j < 4; j++) {
            float4 pv = make_float4(s[0][j], s[1][j], s[2][j], s[3][j]);
            *(float4*)&Ps[(tx * 4 + j) * APAD + ty * 4] = pv;
        }
        __syncthreads();

        // O += P @ V (packed along t)
        #pragma unroll 8
        for (int n = 0; n < 64; n++) {
            ulonglong2 pa = *(const ulonglong2*)&Ps[n * APAD + ty * 4];
            float4 vv = *(const float4*)&Vs[n * APAD + tx * 4];
            u64 b0 = pack2(vv.x, vv.x), b1 = pack2(vv.y, vv.y);
            u64 b2 = pack2(vv.z, vv.z), b3 = pack2(vv.w, vv.w);
            o2[0][0] = fma2(pa.x, b0, o2[0][0]);
            o2[1][0] = fma2(pa.y, b0, o2[1][0]);
            o2[0][1] = fma2(pa.x, b1, o2[0][1]);
            o2[1][1] = fma2(pa.y, b1, o2[1][1]);
            o2[0][2] = fma2(pa.x, b2, o2[0][2]);
            o2[1][2] = fma2(pa.y, b2, o2[1][2]);
            o2[0][3] = fma2(pa.x, b3, o2[0][3]);
            o2[1][3] = fma2(pa.y, b3, o2[1][3]);
        }
    }

    #pragma unroll
    for (int ii = 0; ii < 2; ii++) {
        float lo[4], hi[4];
        #pragma unroll
        for (int j = 0; j < 4; j++) unpack2(o2[ii][j], lo[j], hi[j]);
        float inv0 = 1.f / l[2 * ii], inv1 = 1.f / l[2 * ii + 1];
        #pragma unroll
        for (int j = 0; j < 4; j++) { lo[j] *= inv0; hi[j] *= inv1; }
        size_t r0 = (size_t)(b * TLEN + t0 + ty * 4 + 2 * ii);
        *(float4*)&O[r0 * DIM + h * HDIM + tx * 4]       = *(float4*)&lo[0];
        *(float4*)&O[(r0 + 1) * DIM + h * HDIM + tx * 4] = *(float4*)&hi[0];
    }
}

// ---------------------------------------------------------------------------
extern "C" void kernel_launch(void* const* d_in, const int* in_sizes, int n_in,
                              void* d_out, int out_size) {
    const float* text     = (const float*)d_in[0];
    const float* features = (const float*)d_in[1];
    const float* W_q      = (const float*)d_in[2];
    const float* b_q      = (const float*)d_in[3];
    const float* W_k      = (const float*)d_in[4];
    const float* b_k      = (const float*)d_in[5];
    const float* W_o      = (const float*)d_in[6];
    const float* b_o      = (const float*)d_in[7];
    const float* g_feat   = (const float*)d_in[8];
    const float* g_q      = (const float*)d_in[9];
    const float* g_k      = (const float*)d_in[10];
    float* out = (float*)d_out;

    float *feats, *Qb, *Kb, *Ab;
    cudaGetSymbolAddress((void**)&feats, g_feats);
    cudaGetSymbolAddress((void**)&Qb,    g_Qbuf);
    cudaGetSymbolAddress((void**)&Kb,    g_Kbuf);
    cudaGetSymbolAddress((void**)&Ab,    g_Abuf);

    static int attn_smem_set = 0;
    const int ATTN_SMEM = 4 * 64 * APAD * sizeof(float);  // 69632
    if (!attn_smem_set) {
        cudaFuncSetAttribute(attn_kernel,
                             cudaFuncAttributeMaxDynamicSharedMemorySize, ATTN_SMEM);
        attn_smem_set = 1;
    }

    // 1. feats = rmsnorm(features, g_feat)
    rmsnorm_kernel<<<BATCH * NLEN, 256>>>(features, g_feat, feats);

    // 2. Q = rmsnorm(text @ Wq^T + bq, g_q)
    gemm_bias_kernel<<<dim3(DIM / 128, (BATCH * TLEN) / 128), 256>>>(text, W_q, b_q, Qb);
    rmsnorm_kernel<<<BATCH * TLEN, 256>>>(Qb, g_q, Qb);

    // 3. K = rmsnorm(feats @ Wk^T + bk, g_k)
    gemm_bias_kernel<<<dim3(DIM / 128, (BATCH * NLEN) / 128), 256>>>(feats, W_k, b_k, Kb);
    rmsnorm_kernel<<<BATCH * NLEN, 256>>>(Kb, g_k, Kb);

    // 4. attention
    attn_kernel<<<dim3(BATCH * HEADS, TLEN / 64), 256, ATTN_SMEM>>>(Qb, Kb, feats, Ab);

    // 5. out = Ab @ Wo^T + bo
    gemm_bias_kernel<<<dim3(DIM / 128, (BATCH * TLEN) / 128), 256>>>(Ab, W_o, b_o, out);
}

// round 5
// speedup vs baseline: 1.8967x; 1.4227x over previous
#include <cuda_runtime.h>
#include <cuda_bf16.h>
#include <math.h>

#define BATCH 8
#define TLEN 512
#define NLEN 1024
#define DIM 1024
#define HEADS 16
#define HDIM 64

typedef unsigned long long u64;
typedef unsigned int u32;

// ---------------- fp32x2 helpers (attention) ----------------
__device__ __forceinline__ u64 fma2(u64 a, u64 b, u64 c) {
    u64 d;
    asm("fma.rn.f32x2 %0, %1, %2, %3;" : "=l"(d) : "l"(a), "l"(b), "l"(c));
    return d;
}
__device__ __forceinline__ u64 mul2(u64 a, u64 b) {
    u64 d;
    asm("mul.rn.f32x2 %0, %1, %2;" : "=l"(d) : "l"(a), "l"(b));
    return d;
}
__device__ __forceinline__ u64 pack2(float lo, float hi) {
    u64 d;
    asm("mov.b64 %0, {%1, %2};" : "=l"(d) : "f"(lo), "f"(hi));
    return d;
}
__device__ __forceinline__ void unpack2(u64 v, float& lo, float& hi) {
    asm("mov.b64 {%0, %1}, %2;" : "=f"(lo), "=f"(hi) : "l"(v));
}

// ---------------- mma.sync helpers ----------------
__device__ __forceinline__ u32 smem_u32(const void* p) {
    u32 a;
    asm("{ .reg .u64 t; cvta.to.shared.u64 t, %1; cvt.u32.u64 %0, t; }"
        : "=r"(a) : "l"(p));
    return a;
}
__device__ __forceinline__ void ldsm4(u32& r0, u32& r1, u32& r2, u32& r3, u32 addr) {
    asm volatile("ldmatrix.sync.aligned.m8n8.x4.shared.b16 {%0,%1,%2,%3}, [%4];"
                 : "=r"(r0), "=r"(r1), "=r"(r2), "=r"(r3) : "r"(addr));
}
__device__ __forceinline__ void mma_bf16(float* c, const u32* a, const u32* b) {
    asm volatile(
        "mma.sync.aligned.m16n8k16.row.col.f32.bf16.bf16.f32 "
        "{%0,%1,%2,%3}, {%4,%5,%6,%7}, {%8,%9}, {%0,%1,%2,%3};"
        : "+f"(c[0]), "+f"(c[1]), "+f"(c[2]), "+f"(c[3])
        : "r"(a[0]), "r"(a[1]), "r"(a[2]), "r"(a[3]), "r"(b[0]), "r"(b[1]));
}
__device__ __forceinline__ void cpa(u32 s, const void* g) {
    asm volatile("cp.async.cg.shared.global [%0], [%1], 16;" :: "r"(s), "l"(g));
}

// ---------------- scratch (no cudaMalloc) ----------------
__device__ float g_feats[BATCH * NLEN * DIM];
__device__ float g_Qbuf [BATCH * TLEN * DIM];
__device__ float g_Kbuf [BATCH * NLEN * DIM];

__device__ __nv_bfloat16 g_th[BATCH * TLEN * DIM];
__device__ __nv_bfloat16 g_tl[BATCH * TLEN * DIM];
__device__ __nv_bfloat16 g_fh[BATCH * NLEN * DIM];
__device__ __nv_bfloat16 g_fl[BATCH * NLEN * DIM];
__device__ __nv_bfloat16 g_ah[BATCH * TLEN * DIM];
__device__ __nv_bfloat16 g_al[BATCH * TLEN * DIM];
__device__ __nv_bfloat16 g_wqh[DIM * DIM];
__device__ __nv_bfloat16 g_wql[DIM * DIM];
__device__ __nv_bfloat16 g_wkh[DIM * DIM];
__device__ __nv_bfloat16 g_wkl[DIM * DIM];
__device__ __nv_bfloat16 g_woh[DIM * DIM];
__device__ __nv_bfloat16 g_wol[DIM * DIM];

// ---------------------------------------------------------------------------
// Split fp32 -> bf16 hi/lo
// ---------------------------------------------------------------------------
__global__ void convert_split_kernel(const float* __restrict__ in,
                                     __nv_bfloat16* __restrict__ hi,
                                     __nv_bfloat16* __restrict__ lo) {
    int i = blockIdx.x * blockDim.x + threadIdx.x;
    float4 v = ((const float4*)in)[i];
    __nv_bfloat16 h0 = __float2bfloat16(v.x);
    __nv_bfloat16 h1 = __float2bfloat16(v.y);
    __nv_bfloat16 h2 = __float2bfloat16(v.z);
    __nv_bfloat16 h3 = __float2bfloat16(v.w);
    __nv_bfloat16 l0 = __float2bfloat16(v.x - __bfloat162float(h0));
    __nv_bfloat16 l1 = __float2bfloat16(v.y - __bfloat162float(h1));
    __nv_bfloat16 l2 = __float2bfloat16(v.z - __bfloat162float(h2));
    __nv_bfloat16 l3 = __float2bfloat16(v.w - __bfloat162float(h3));
    __nv_bfloat162* H = (__nv_bfloat162*)hi;
    __nv_bfloat162* L = (__nv_bfloat162*)lo;
    H[2 * i]     = __nv_bfloat162(h0, h1);
    H[2 * i + 1] = __nv_bfloat162(h2, h3);
    L[2 * i]     = __nv_bfloat162(l0, l1);
    L[2 * i + 1] = __nv_bfloat162(l2, l3);
}

// ---------------------------------------------------------------------------
// RMSNorm over rows of DIM=1024 (fp32 out)
// ---------------------------------------------------------------------------
__global__ void rmsnorm_kernel(const float* __restrict__ in,
                               const float* __restrict__ g,
                               float* __restrict__ out) {
    int row = blockIdx.x;
    int tid = threadIdx.x;
    const float4* x4 = (const float4*)(in + (size_t)row * DIM);
    float4 v = x4[tid];
    float s = v.x * v.x + v.y * v.y + v.z * v.z + v.w * v.w;
    #pragma unroll
    for (int o = 16; o > 0; o >>= 1) s += __shfl_xor_sync(0xffffffffu, s, o);
    __shared__ float ws[8];
    __shared__ float rsh;
    if ((tid & 31) == 0) ws[tid >> 5] = s;
    __syncthreads();
    if (tid == 0) {
        float t = 0.f;
        #pragma unroll
        for (int i = 0; i < 8; i++) t += ws[i];
        rsh = rsqrtf(t * (1.0f / DIM) + 1e-6f);
    }
    __syncthreads();
    float r = rsh;
    float4 gv = ((const float4*)g)[tid];
    float4 ov = make_float4(v.x * r * gv.x, v.y * r * gv.y,
                            v.z * r * gv.z, v.w * r * gv.w);
    ((float4*)(out + (size_t)row * DIM))[tid] = ov;
}

// ---------------------------------------------------------------------------
// RMSNorm + bf16 hi/lo split (for features)
// ---------------------------------------------------------------------------
__global__ void rmsnorm_split_kernel(const float* __restrict__ in,
                                     const float* __restrict__ g,
                                     float* __restrict__ out,
                                     __nv_bfloat16* __restrict__ hi,
                                     __nv_bfloat16* __restrict__ lo) {
    int row = blockIdx.x;
    int tid = threadIdx.x;
    const float4* x4 = (const float4*)(in + (size_t)row * DIM);
    float4 v = x4[tid];
    float s = v.x * v.x + v.y * v.y + v.z * v.z + v.w * v.w;
    #pragma unroll
    for (int o = 16; o > 0; o >>= 1) s += __shfl_xor_sync(0xffffffffu, s, o);
    __shared__ float ws[8];
    __shared__ float rsh;
    if ((tid & 31) == 0) ws[tid >> 5] = s;
    __syncthreads();
    if (tid == 0) {
        float t = 0.f;
        #pragma unroll
        for (int i = 0; i < 8; i++) t += ws[i];
        rsh = rsqrtf(t * (1.0f / DIM) + 1e-6f);
    }
    __syncthreads();
    float r = rsh;
    float4 gv = ((const float4*)g)[tid];
    float4 ov = make_float4(v.x * r * gv.x, v.y * r * gv.y,
                            v.z * r * gv.z, v.w * r * gv.w);
    ((float4*)(out + (size_t)row * DIM))[tid] = ov;

    __nv_bfloat16 h0 = __float2bfloat16(ov.x);
    __nv_bfloat16 h1 = __float2bfloat16(ov.y);
    __nv_bfloat16 h2 = __float2bfloat16(ov.z);
    __nv_bfloat16 h3 = __float2bfloat16(ov.w);
    __nv_bfloat16 l0 = __float2bfloat16(ov.x - __bfloat162float(h0));
    __nv_bfloat16 l1 = __float2bfloat16(ov.y - __bfloat162float(h1));
    __nv_bfloat16 l2 = __float2bfloat16(ov.z - __bfloat162float(h2));
    __nv_bfloat16 l3 = __float2bfloat16(ov.w - __bfloat162float(h3));
    size_t base = (size_t)row * DIM + tid * 4;
    __nv_bfloat162* H = (__nv_bfloat162*)(hi + base);
    __nv_bfloat162* L = (__nv_bfloat162*)(lo + base);
    H[0] = __nv_bfloat162(h0, h1); H[1] = __nv_bfloat162(h2, h3);
    L[0] = __nv_bfloat162(l0, l1); L[1] = __nv_bfloat162(l2, l3);
}

// ---------------------------------------------------------------------------
// Tensor-core GEMM via mma.sync: C[M,1024] = A[M,1024] @ W[1024,1024]^T + bias
// bf16 3-term split (Ah*Wh + Ah*Wl + Al*Wh), fp32 accumulate.
// CTA 128x128, 8 warps (2x4), warp 64x32, K-chunks 64, cp.async double buffer.
// smem/stage: Ah|Al|Wh|Wl each 128x64 bf16 (16KB, XOR-swizzled 128B rows).
// ---------------------------------------------------------------------------
#define MM_SMEM (2 * 4 * 16384)
__global__ __launch_bounds__(256, 1)
void mma_gemm_kernel(const __nv_bfloat16* __restrict__ Ah,
                     const __nv_bfloat16* __restrict__ Al,
                     const __nv_bfloat16* __restrict__ Wh,
                     const __nv_bfloat16* __restrict__ Wl,
                     const float* __restrict__ bias,
                     float* __restrict__ C) {
    extern __shared__ char smem[];
    const u32 sb = smem_u32(smem);
    int tid  = threadIdx.x;
    int wid  = tid >> 5, lane = tid & 31;
    int bm = blockIdx.y * 128, bn = blockIdx.x * 128;
    int wm = (wid >> 2) * 64;
    int wn = (wid & 3) * 32;

    // global load mapping: thread -> (row, half of 64-bf16 chunk)
    int lrow  = tid >> 1;
    int lhalf = tid & 1;
    const char* gAh = (const char*)(Ah + (size_t)(bm + lrow) * DIM) + lhalf * 64;
    const char* gAl = (const char*)(Al + (size_t)(bm + lrow) * DIM) + lhalf * 64;
    const char* gWh = (const char*)(Wh + (size_t)(bn + lrow) * DIM) + lhalf * 64;
    const char* gWl = (const char*)(Wl + (size_t)(bn + lrow) * DIM) + lhalf * 64;

    float acc[4][4][4];
    #pragma unroll
    for (int mi = 0; mi < 4; mi++)
        #pragma unroll
        for (int n = 0; n < 4; n++)
            #pragma unroll
            for (int q = 0; q < 4; q++) acc[mi][n][q] = 0.f;

    // fragment addressing
    int rA = wm + (lane & 15);
    int rW = wn + (lane & 15);
    u32 aRow = sb + (u32)rA * 128;
    u32 wRow = sb + (u32)rW * 128;
    int uu  = lane >> 4;
    int sA7 = rA & 7, sW7 = rW & 7;

    auto issue_stage = [&](int stage, int c) {
        u32 base = sb + (u32)stage * 65536 + (u32)lrow * 128;
        const char* pa = gAh + c * 128;
        const char* pb = gAl + c * 128;
        const char* pc = gWh + c * 128;
        const char* pd = gWl + c * 128;
        #pragma unroll
        for (int j = 0; j < 4; j++) {
            int u = lhalf * 4 + j;
            u32 sw = (u32)((u ^ (lrow & 7)) << 4);
            cpa(base +         sw, pa + j * 16);
            cpa(base + 16384 + sw, pb + j * 16);
            cpa(base + 32768 + sw, pc + j * 16);
            cpa(base + 49152 + sw, pd + j * 16);
        }
        asm volatile("cp.async.commit_group;" ::: "memory");
    };

    issue_stage(0, 0);

    for (int c = 0; c < 16; c++) {
        int buf = c & 1;
        if (c + 1 < 16) {
            issue_stage(buf ^ 1, c + 1);
            asm volatile("cp.async.wait_group 1;" ::: "memory");
        } else {
            asm volatile("cp.async.wait_group 0;" ::: "memory");
        }
        __syncthreads();

        u32 stb = (u32)buf * 65536;
        #pragma unroll
        for (int ks = 0; ks < 4; ks++) {
            u32 swA = (u32)(((ks * 2 + uu) ^ sA7) << 4);
            u32 swW = (u32)(((ks * 2 + uu) ^ sW7) << 4);
            u32 ahf[4][4], alf[4][4], whf[4][2], wlf[4][2];
            #pragma unroll
            for (int mi = 0; mi < 4; mi++) {
                ldsm4(ahf[mi][0], ahf[mi][1], ahf[mi][2], ahf[mi][3],
                      aRow + stb + (u32)mi * 2048 + swA);
                ldsm4(alf[mi][0], alf[mi][1], alf[mi][2], alf[mi][3],
                      aRow + stb + 16384 + (u32)mi * 2048 + swA);
            }
            #pragma unroll
            for (int nj = 0; nj < 2; nj++) {
                u32 r0, r1, r2, r3;
                ldsm4(r0, r1, r2, r3, wRow + stb + 32768 + (u32)nj * 2048 + swW);
                whf[2 * nj][0] = r0; whf[2 * nj + 1][0] = r1;
                whf[2 * nj][1] = r2; whf[2 * nj + 1][1] = r3;
                ldsm4(r0, r1, r2, r3, wRow + stb + 49152 + (u32)nj * 2048 + swW);
                wlf[2 * nj][0] = r0; wlf[2 * nj + 1][0] = r1;
                wlf[2 * nj][1] = r2; wlf[2 * nj + 1][1] = r3;
            }
            #pragma unroll
            for (int mi = 0; mi < 4; mi++)
                #pragma unroll
                for (int n = 0; n < 4; n++) {
                    mma_bf16(acc[mi][n], ahf[mi], whf[n]);
                    mma_bf16(acc[mi][n], ahf[mi], wlf[n]);
                    mma_bf16(acc[mi][n], alf[mi], whf[n]);
                }
        }
        __syncthreads();
    }

    // epilogue
    int er = lane >> 2, ec = (lane & 3) * 2;
    #pragma unroll
    for (int mi = 0; mi < 4; mi++) {
        int row0 = bm + wm + mi * 16 + er;
        #pragma unroll
        for (int n = 0; n < 4; n++) {
            int col = bn + wn + n * 8 + ec;
            float2 bv = *(const float2*)&bias[col];
            float2 v0 = make_float2(acc[mi][n][0] + bv.x, acc[mi][n][1] + bv.y);
            float2 v1 = make_float2(acc[mi][n][2] + bv.x, acc[mi][n][3] + bv.y);
            *(float2*)&C[(size_t)row0 * DIM + col]       = v0;
            *(float2*)&C[(size_t)(row0 + 8) * DIM + col] = v1;
        }
    }
}

// ---------------------------------------------------------------------------
// Flash attention (SIMT, f32x2); epilogue writes bf16 hi/lo split of output.
// ---------------------------------------------------------------------------
#define APAD 68
__global__ __launch_bounds__(256)
void attn_kernel(const float* __restrict__ Q, const float* __restrict__ K,
                 const float* __restrict__ V,
                 __nv_bfloat16* __restrict__ OH, __nv_bfloat16* __restrict__ OL) {
    extern __shared__ float sm[];
    float* Qt = sm;
    float* Kt = sm + 64 * APAD;
    float* Vs = Kt + 64 * APAD;
    float* Ps = Vs + 64 * APAD;

    int b  = blockIdx.x >> 4;
    int h  = blockIdx.x & 15;
    int t0 = blockIdx.y * 64;
    int tid = threadIdx.x;
    int tx = tid & 15;
    int ty = tid >> 4;

    for (int i = tid; i < 1024; i += 256) {
        int t = i >> 4, d = (i & 15) << 2;
        float4 q = *(const float4*)&Q[((size_t)(b * TLEN + t0 + t)) * DIM + h * HDIM + d];
        Qt[(d + 0) * APAD + t] = q.x * 0.125f;
        Qt[(d + 1) * APAD + t] = q.y * 0.125f;
        Qt[(d + 2) * APAD + t] = q.z * 0.125f;
        Qt[(d + 3) * APAD + t] = q.w * 0.125f;
    }

    u64 o2[2][4];
    float m[4], l[4];
    #pragma unroll
    for (int i = 0; i < 4; i++) { m[i] = -INFINITY; l[i] = 0.f; }
    #pragma unroll
    for (int ii = 0; ii < 2; ii++)
        #pragma unroll
        for (int j = 0; j < 4; j++) o2[ii][j] = 0ull;

    for (int n0 = 0; n0 < NLEN; n0 += 64) {
        __syncthreads();
        for (int i = tid; i < 1024; i += 256) {
            int n = i >> 4, d = (i & 15) << 2;
            size_t gb = ((size_t)(b * NLEN + n0 + n)) * DIM + h * HDIM + d;
            float4 kv = *(const float4*)&K[gb];
            Kt[(d + 0) * APAD + n] = kv.x;
            Kt[(d + 1) * APAD + n] = kv.y;
            Kt[(d + 2) * APAD + n] = kv.z;
            Kt[(d + 3) * APAD + n] = kv.w;
            float4 vv = *(const float4*)&V[gb];
            *(float4*)&Vs[n * APAD + d] = vv;
        }
        __syncthreads();

        u64 s2[2][4];
        #pragma unroll
        for (int ii = 0; ii < 2; ii++)
            #pragma unroll
            for (int j = 0; j < 4; j++) s2[ii][j] = 0ull;
        #pragma unroll 8
        for (int d = 0; d < 64; d++) {
            ulonglong2 qa = *(const ulonglong2*)&Qt[d * APAD + ty * 4];
            float4 kv = *(const float4*)&Kt[d * APAD + tx * 4];
            u64 b0 = pack2(kv.x, kv.x), b1 = pack2(kv.y, kv.y);
            u64 b2 = pack2(kv.z, kv.z), b3 = pack2(kv.w, kv.w);
            s2[0][0] = fma2(qa.x, b0, s2[0][0]);
            s2[1][0] = fma2(qa.y, b0, s2[1][0]);
            s2[0][1] = fma2(qa.x, b1, s2[0][1]);
            s2[1][1] = fma2(qa.y, b1, s2[1][1]);
            s2[0][2] = fma2(qa.x, b2, s2[0][2]);
            s2[1][2] = fma2(qa.y, b2, s2[1][2]);
            s2[0][3] = fma2(qa.x, b3, s2[0][3]);
            s2[1][3] = fma2(qa.y, b3, s2[1][3]);
        }

        float s[4][4];
        #pragma unroll
        for (int ii = 0; ii < 2; ii++)
            #pragma unroll
            for (int j = 0; j < 4; j++)
                unpack2(s2[ii][j], s[2 * ii][j], s[2 * ii + 1][j]);

        float sc[4];
        #pragma unroll
        for (int i = 0; i < 4; i++) {
            float cm = fmaxf(fmaxf(s[i][0], s[i][1]), fmaxf(s[i][2], s[i][3]));
            cm = fmaxf(cm, __shfl_xor_sync(0xffffffffu, cm, 1));
            cm = fmaxf(cm, __shfl_xor_sync(0xffffffffu, cm, 2));
            cm = fmaxf(cm, __shfl_xor_sync(0xffffffffu, cm, 4));
            cm = fmaxf(cm, __shfl_xor_sync(0xffffffffu, cm, 8));
            float mn = fmaxf(m[i], cm);
            sc[i] = __expf(m[i] - mn);
            m[i] = mn;
            float rs = 0.f;
            #pragma unroll
            for (int j = 0; j < 4; j++) {
                s[i][j] = __expf(s[i][j] - mn);
                rs += s[i][j];
            }
            rs += __shfl_xor_sync(0xffffffffu, rs, 1);
            rs += __shfl_xor_sync(0xffffffffu, rs, 2);
            rs += __shfl_xor_sync(0xffffffffu, rs, 4);
            rs += __shfl_xor_sync(0xffffffffu, rs, 8);
            l[i] = l[i] * sc[i] + rs;
        }
        #pragma unroll
        for (int ii = 0; ii < 2; ii++) {
            u64 scp = pack2(sc[2 * ii], sc[2 * ii + 1]);
            #pragma unroll
            for (int j = 0; j < 4; j++) o2[ii][j] = mul2(o2[ii][j], scp);
        }

        #pragma unroll
        for (int j = 0; j < 4; j++) {
            float4 pv = make_float4(s[0][j], s[1][j], s[2][j], s[3][j]);
            *(float4*)&Ps[(tx * 4 + j) * APAD + ty * 4] = pv;
        }
        __syncthreads();

        #pragma unroll 8
        for (int n = 0; n < 64; n++) {
            ulonglong2 pa = *(const ulonglong2*)&Ps[n * APAD + ty * 4];
            float4 vv = *(const float4*)&Vs[n * APAD + tx * 4];
            u64 b0 = pack2(vv.x, vv.x), b1 = pack2(vv.y, vv.y);
            u64 b2 = pack2(vv.z, vv.z), b3 = pack2(vv.w, vv.w);
            o2[0][0] = fma2(pa.x, b0, o2[0][0]);
            o2[1][0] = fma2(pa.y, b0, o2[1][0]);
            o2[0][1] = fma2(pa.x, b1, o2[0][1]);
            o2[1][1] = fma2(pa.y, b1, o2[1][1]);
            o2[0][2] = fma2(pa.x, b2, o2[0][2]);
            o2[1][2] = fma2(pa.y, b2, o2[1][2]);
            o2[0][3] = fma2(pa.x, b3, o2[0][3]);
            o2[1][3] = fma2(pa.y, b3, o2[1][3]);
        }
    }

    #pragma unroll
    for (int ii = 0; ii < 2; ii++) {
        float lo[4], hi[4];
        #pragma unroll
        for (int j = 0; j < 4; j++) unpack2(o2[ii][j], lo[j], hi[j]);
        float inv0 = 1.f / l[2 * ii], inv1 = 1.f / l[2 * ii + 1];
        #pragma unroll
        for (int j = 0; j < 4; j++) { lo[j] *= inv0; hi[j] *= inv1; }
        size_t r0 = (size_t)(b * TLEN + t0 + ty * 4 + 2 * ii);
        size_t i0 = r0 * DIM + h * HDIM + tx * 4;
        size_t i1 = (r0 + 1) * DIM + h * HDIM + tx * 4;
        // bf16 hi/lo split stores (4 bf16 = 8 bytes each)
        #pragma unroll
        for (int rr = 0; rr < 2; rr++) {
            float* v = rr ? hi : lo;
            size_t idx = rr ? i1 : i0;
            __nv_bfloat16 h0 = __float2bfloat16(v[0]);
            __nv_bfloat16 h1 = __float2bfloat16(v[1]);
            __nv_bfloat16 h2 = __float2bfloat16(v[2]);
            __nv_bfloat16 h3 = __float2bfloat16(v[3]);
            __nv_bfloat16 e0 = __float2bfloat16(v[0] - __bfloat162float(h0));
            __nv_bfloat16 e1 = __float2bfloat16(v[1] - __bfloat162float(h1));
            __nv_bfloat16 e2 = __float2bfloat16(v[2] - __bfloat162float(h2));
            __nv_bfloat16 e3 = __float2bfloat16(v[3] - __bfloat162float(h3));
            __nv_bfloat162* H = (__nv_bfloat162*)(OH + idx);
            __nv_bfloat162* L = (__nv_bfloat162*)(OL + idx);
            H[0] = __nv_bfloat162(h0, h1); H[1] = __nv_bfloat162(h2, h3);
            L[0] = __nv_bfloat162(e0, e1); L[1] = __nv_bfloat162(e2, e3);
        }
    }
}

// ---------------------------------------------------------------------------
extern "C" void kernel_launch(void* const* d_in, const int* in_sizes, int n_in,
                              void* d_out, int out_size) {
    const float* text     = (const float*)d_in[0];
    const float* features = (const float*)d_in[1];
    const float* W_q      = (const float*)d_in[2];
    const float* b_q      = (const float*)d_in[3];
    const float* W_k      = (const float*)d_in[4];
    const float* b_k      = (const float*)d_in[5];
    const float* W_o      = (const float*)d_in[6];
    const float* b_o      = (const float*)d_in[7];
    const float* g_feat   = (const float*)d_in[8];
    const float* g_q      = (const float*)d_in[9];
    const float* g_k      = (const float*)d_in[10];
    float* out = (float*)d_out;

    float *feats, *Qb, *Kb;
    cudaGetSymbolAddress((void**)&feats, g_feats);
    cudaGetSymbolAddress((void**)&Qb,    g_Qbuf);
    cudaGetSymbolAddress((void**)&Kb,    g_Kbuf);

    __nv_bfloat16 *th, *tl, *fh, *fl, *ah, *al;
    __nv_bfloat16 *wqh, *wql, *wkh, *wkl, *woh, *wol;
    cudaGetSymbolAddress((void**)&th,  g_th);
    cudaGetSymbolAddress((void**)&tl,  g_tl);
    cudaGetSymbolAddress((void**)&fh,  g_fh);
    cudaGetSymbolAddress((void**)&fl,  g_fl);
    cudaGetSymbolAddress((void**)&ah,  g_ah);
    cudaGetSymbolAddress((void**)&al,  g_al);
    cudaGetSymbolAddress((void**)&wqh, g_wqh);
    cudaGetSymbolAddress((void**)&wql, g_wql);
    cudaGetSymbolAddress((void**)&wkh, g_wkh);
    cudaGetSymbolAddress((void**)&wkl, g_wkl);
    cudaGetSymbolAddress((void**)&woh, g_woh);
    cudaGetSymbolAddress((void**)&wol, g_wol);

    static int attrs_set = 0;
    const int ATTN_SMEM = 4 * 64 * APAD * sizeof(float);
    if (!attrs_set) {
        cudaFuncSetAttribute(attn_kernel,
                             cudaFuncAttributeMaxDynamicSharedMemorySize, ATTN_SMEM);
        cudaFuncSetAttribute(mma_gemm_kernel,
                             cudaFuncAttributeMaxDynamicSharedMemorySize, MM_SMEM);
        attrs_set = 1;
    }

    const int MT = BATCH * TLEN;   // 4096
    const int MN = BATCH * NLEN;   // 8192

    // 1. feats = rmsnorm(features) (+ bf16 split for K-GEMM)
    rmsnorm_split_kernel<<<MN, 256>>>(features, g_feat, feats, fh, fl);

    // 2. bf16 splits of text + weights
    convert_split_kernel<<<(MT * DIM / 4) / 256, 256>>>(text, th, tl);
    convert_split_kernel<<<(DIM * DIM / 4) / 256, 256>>>(W_q, wqh, wql);
    convert_split_kernel<<<(DIM * DIM / 4) / 256, 256>>>(W_k, wkh, wkl);
    convert_split_kernel<<<(DIM * DIM / 4) / 256, 256>>>(W_o, woh, wol);

    // 3. Q = rmsnorm(text @ Wq^T + bq)
    mma_gemm_kernel<<<dim3(8, MT / 128), 256, MM_SMEM>>>(th, tl, wqh, wql, b_q, Qb);
    rmsnorm_kernel<<<MT, 256>>>(Qb, g_q, Qb);

    // 4. K = rmsnorm(feats @ Wk^T + bk)
    mma_gemm_kernel<<<dim3(8, MN / 128), 256, MM_SMEM>>>(fh, fl, wkh, wkl, b_k, Kb);
    rmsnorm_kernel<<<MN, 256>>>(Kb, g_k, Kb);

    // 5. attention (writes bf16 hi/lo split of output directly)
    attn_kernel<<<dim3(BATCH * HEADS, TLEN / 64), 256, ATTN_SMEM>>>(Qb, Kb, feats, ah, al);

    // 6. out = attnOut @ Wo^T + bo
    mma_gemm_kernel<<<dim3(8, MT / 128), 256, MM_SMEM>>>(ah, al, woh, wol, b_o, out);
}

// round 6
// speedup vs baseline: 2.8979x; 1.5279x over previous
#include <cuda_runtime.h>
#include <cuda_bf16.h>
#include <math.h>

#define BATCH 8
#define TLEN 512
#define NLEN 1024
#define DIM 1024
#define HEADS 16
#define HDIM 64

typedef unsigned long long u64;
typedef unsigned int u32;

// ---------------- mma.sync helpers ----------------
__device__ __forceinline__ u32 smem_u32(const void* p) {
    u32 a;
    asm("{ .reg .u64 t; cvta.to.shared.u64 t, %1; cvt.u32.u64 %0, t; }"
        : "=r"(a) : "l"(p));
    return a;
}
__device__ __forceinline__ void ldsm4(u32& r0, u32& r1, u32& r2, u32& r3, u32 addr) {
    asm volatile("ldmatrix.sync.aligned.m8n8.x4.shared.b16 {%0,%1,%2,%3}, [%4];"
                 : "=r"(r0), "=r"(r1), "=r"(r2), "=r"(r3) : "r"(addr));
}
__device__ __forceinline__ void mma_bf16(float* c, const u32* a, const u32* b) {
    asm volatile(
        "mma.sync.aligned.m16n8k16.row.col.f32.bf16.bf16.f32 "
        "{%0,%1,%2,%3}, {%4,%5,%6,%7}, {%8,%9}, {%0,%1,%2,%3};"
        : "+f"(c[0]), "+f"(c[1]), "+f"(c[2]), "+f"(c[3])
        : "r"(a[0]), "r"(a[1]), "r"(a[2]), "r"(a[3]), "r"(b[0]), "r"(b[1]));
}
__device__ __forceinline__ void cpa(u32 s, const void* g) {
    asm volatile("cp.async.cg.shared.global [%0], [%1], 16;" :: "r"(s), "l"(g));
}
// pack (lo, hi) floats -> bf16x2 reg (lo in low half)
__device__ __forceinline__ u32 pack_bf16(float lo, float hi) {
    u32 r;
    asm("cvt.rn.bf16x2.f32 %0, %1, %2;" : "=r"(r) : "f"(hi), "f"(lo));
    return r;
}
// residual pack: (lo - bf16(lo), hi - bf16(hi)) given the hi-pack
__device__ __forceinline__ u32 pack_resid(u32 hp, float lo, float hi) {
    float rl = lo - __bfloat162float(__ushort_as_bfloat16((unsigned short)(hp & 0xFFFFu)));
    float rh = hi - __bfloat162float(__ushort_as_bfloat16((unsigned short)(hp >> 16)));
    return pack_bf16(rl, rh);
}

// ---------------- scratch (no cudaMalloc) ----------------
__device__ float g_Qbuf[BATCH * TLEN * DIM];
__device__ float g_Kbuf[BATCH * NLEN * DIM];

__device__ __nv_bfloat16 g_th[BATCH * TLEN * DIM];
__device__ __nv_bfloat16 g_tl[BATCH * TLEN * DIM];
__device__ __nv_bfloat16 g_fh[BATCH * NLEN * DIM];
__device__ __nv_bfloat16 g_fl[BATCH * NLEN * DIM];
__device__ __nv_bfloat16 g_ah[BATCH * TLEN * DIM];
__device__ __nv_bfloat16 g_al[BATCH * TLEN * DIM];
__device__ __nv_bfloat16 g_qh[BATCH * TLEN * DIM];
__device__ __nv_bfloat16 g_ql[BATCH * TLEN * DIM];
__device__ __nv_bfloat16 g_kh[BATCH * NLEN * DIM];
__device__ __nv_bfloat16 g_kl[BATCH * NLEN * DIM];
__device__ __nv_bfloat16 g_vth[BATCH * NLEN * DIM];
__device__ __nv_bfloat16 g_vtl[BATCH * NLEN * DIM];
__device__ __nv_bfloat16 g_wqh[DIM * DIM];
__device__ __nv_bfloat16 g_wql[DIM * DIM];
__device__ __nv_bfloat16 g_wkh[DIM * DIM];
__device__ __nv_bfloat16 g_wkl[DIM * DIM];
__device__ __nv_bfloat16 g_woh[DIM * DIM];
__device__ __nv_bfloat16 g_wol[DIM * DIM];

// ---------------------------------------------------------------------------
// Split fp32 -> bf16 hi/lo
// ---------------------------------------------------------------------------
__global__ void convert_split_kernel(const float* __restrict__ in,
                                     __nv_bfloat16* __restrict__ hi,
                                     __nv_bfloat16* __restrict__ lo) {
    int i = blockIdx.x * blockDim.x + threadIdx.x;
    float4 v = ((const float4*)in)[i];
    __nv_bfloat16 h0 = __float2bfloat16(v.x);
    __nv_bfloat16 h1 = __float2bfloat16(v.y);
    __nv_bfloat16 h2 = __float2bfloat16(v.z);
    __nv_bfloat16 h3 = __float2bfloat16(v.w);
    __nv_bfloat16 l0 = __float2bfloat16(v.x - __bfloat162float(h0));
    __nv_bfloat16 l1 = __float2bfloat16(v.y - __bfloat162float(h1));
    __nv_bfloat16 l2 = __float2bfloat16(v.z - __bfloat162float(h2));
    __nv_bfloat16 l3 = __float2bfloat16(v.w - __bfloat162float(h3));
    __nv_bfloat162* H = (__nv_bfloat162*)hi;
    __nv_bfloat162* L = (__nv_bfloat162*)lo;
    H[2 * i]     = __nv_bfloat162(h0, h1);
    H[2 * i + 1] = __nv_bfloat162(h2, h3);
    L[2 * i]     = __nv_bfloat162(l0, l1);
    L[2 * i + 1] = __nv_bfloat162(l2, l3);
}

// ---------------------------------------------------------------------------
// RMSNorm -> scaled bf16 hi/lo split (no fp32 output)
// ---------------------------------------------------------------------------
__global__ void rmsnorm_split_kernel(const float* __restrict__ in,
                                     const float* __restrict__ g,
                                     float scale,
                                     __nv_bfloat16* __restrict__ hi,
                                     __nv_bfloat16* __restrict__ lo) {
    int row = blockIdx.x;
    int tid = threadIdx.x;
    const float4* x4 = (const float4*)(in + (size_t)row * DIM);
    float4 v = x4[tid];
    float s = v.x * v.x + v.y * v.y + v.z * v.z + v.w * v.w;
    #pragma unroll
    for (int o = 16; o > 0; o >>= 1) s += __shfl_xor_sync(0xffffffffu, s, o);
    __shared__ float ws[8];
    __shared__ float rsh;
    if ((tid & 31) == 0) ws[tid >> 5] = s;
    __syncthreads();
    if (tid == 0) {
        float t = 0.f;
        #pragma unroll
        for (int i = 0; i < 8; i++) t += ws[i];
        rsh = rsqrtf(t * (1.0f / DIM) + 1e-6f);
    }
    __syncthreads();
    float r = rsh * scale;
    float4 gv = ((const float4*)g)[tid];
    float ox = v.x * r * gv.x, oy = v.y * r * gv.y;
    float oz = v.z * r * gv.z, ow = v.w * r * gv.w;
    __nv_bfloat16 h0 = __float2bfloat16(ox);
    __nv_bfloat16 h1 = __float2bfloat16(oy);
    __nv_bfloat16 h2 = __float2bfloat16(oz);
    __nv_bfloat16 h3 = __float2bfloat16(ow);
    __nv_bfloat16 e0 = __float2bfloat16(ox - __bfloat162float(h0));
    __nv_bfloat16 e1 = __float2bfloat16(oy - __bfloat162float(h1));
    __nv_bfloat16 e2 = __float2bfloat16(oz - __bfloat162float(h2));
    __nv_bfloat16 e3 = __float2bfloat16(ow - __bfloat162float(h3));
    size_t base = (size_t)row * DIM + tid * 4;
    __nv_bfloat162* H = (__nv_bfloat162*)(hi + base);
    __nv_bfloat162* L = (__nv_bfloat162*)(lo + base);
    H[0] = __nv_bfloat162(h0, h1); H[1] = __nv_bfloat162(h2, h3);
    L[0] = __nv_bfloat162(e0, e1); L[1] = __nv_bfloat162(e2, e3);
}

// ---------------------------------------------------------------------------
// Transpose feats splits into V^T per (b,h): vth[bh][d][n] = fh[b*N+n][h*64+d]
// grid (NLEN/32, HDIM/32, BATCH*HEADS), block (32,8)
// ---------------------------------------------------------------------------
__global__ void transpose_vt_kernel(const __nv_bfloat16* __restrict__ fh,
                                    const __nv_bfloat16* __restrict__ fl,
                                    __nv_bfloat16* __restrict__ vth,
                                    __nv_bfloat16* __restrict__ vtl) {
    __shared__ __nv_bfloat16 tH[32][34];
    __shared__ __nv_bfloat16 tL[32][34];
    int bh = blockIdx.z;
    int b = bh >> 4, h = bh & 15;
    int n0 = blockIdx.x * 32, d0 = blockIdx.y * 32;
    int tx = threadIdx.x, ty = threadIdx.y;
    #pragma unroll
    for (int i = 0; i < 4; i++) {
        int n = n0 + ty + i * 8;
        size_t src = (size_t)(b * NLEN + n) * DIM + h * HDIM + d0 + tx;
        tH[ty + i * 8][tx] = fh[src];
        tL[ty + i * 8][tx] = fl[src];
    }
    __syncthreads();
    #pragma unroll
    for (int i = 0; i < 4; i++) {
        int d = d0 + ty + i * 8;
        size_t dst = ((size_t)bh * HDIM + d) * NLEN + n0 + tx;
        vth[dst] = tH[tx][ty + i * 8];
        vtl[dst] = tL[tx][ty + i * 8];
    }
}

// ---------------------------------------------------------------------------
// Tensor-core GEMM (unchanged from round 5, validated)
// ---------------------------------------------------------------------------
#define MM_SMEM (2 * 4 * 16384)
__global__ __launch_bounds__(256, 1)
void mma_gemm_kernel(const __nv_bfloat16* __restrict__ Ah,
                     const __nv_bfloat16* __restrict__ Al,
                     const __nv_bfloat16* __restrict__ Wh,
                     const __nv_bfloat16* __restrict__ Wl,
                     const float* __restrict__ bias,
                     float* __restrict__ C) {
    extern __shared__ char smem[];
    const u32 sb = smem_u32(smem);
    int tid  = threadIdx.x;
    int wid  = tid >> 5, lane = tid & 31;
    int bm = blockIdx.y * 128, bn = blockIdx.x * 128;
    int wm = (wid >> 2) * 64;
    int wn = (wid & 3) * 32;

    int lrow  = tid >> 1;
    int lhalf = tid & 1;
    const char* gAh = (const char*)(Ah + (size_t)(bm + lrow) * DIM) + lhalf * 64;
    const char* gAl = (const char*)(Al + (size_t)(bm + lrow) * DIM) + lhalf * 64;
    const char* gWh = (const char*)(Wh + (size_t)(bn + lrow) * DIM) + lhalf * 64;
    const char* gWl = (const char*)(Wl + (size_t)(bn + lrow) * DIM) + lhalf * 64;

    float acc[4][4][4];
    #pragma unroll
    for (int mi = 0; mi < 4; mi++)
        #pragma unroll
        for (int n = 0; n < 4; n++)
            #pragma unroll
            for (int q = 0; q < 4; q++) acc[mi][n][q] = 0.f;

    int rA = wm + (lane & 15);
    int rW = wn + (lane & 15);
    u32 aRow = sb + (u32)rA * 128;
    u32 wRow = sb + (u32)rW * 128;
    int uu  = lane >> 4;
    int sA7 = rA & 7, sW7 = rW & 7;

    auto issue_stage = [&](int stage, int c) {
        u32 base = sb + (u32)stage * 65536 + (u32)lrow * 128;
        const char* pa = gAh + c * 128;
        const char* pb = gAl + c * 128;
        const char* pc = gWh + c * 128;
        const char* pd = gWl + c * 128;
        #pragma unroll
        for (int j = 0; j < 4; j++) {
            int u = lhalf * 4 + j;
            u32 sw = (u32)((u ^ (lrow & 7)) << 4);
            cpa(base +         sw, pa + j * 16);
            cpa(base + 16384 + sw, pb + j * 16);
            cpa(base + 32768 + sw, pc + j * 16);
            cpa(base + 49152 + sw, pd + j * 16);
        }
        asm volatile("cp.async.commit_group;" ::: "memory");
    };

    issue_stage(0, 0);

    for (int c = 0; c < 16; c++) {
        int buf = c & 1;
        if (c + 1 < 16) {
            issue_stage(buf ^ 1, c + 1);
            asm volatile("cp.async.wait_group 1;" ::: "memory");
        } else {
            asm volatile("cp.async.wait_group 0;" ::: "memory");
        }
        __syncthreads();

        u32 stb = (u32)buf * 65536;
        #pragma unroll
        for (int ks = 0; ks < 4; ks++) {
            u32 swA = (u32)(((ks * 2 + uu) ^ sA7) << 4);
            u32 swW = (u32)(((ks * 2 + uu) ^ sW7) << 4);
            u32 ahf[4][4], alf[4][4], whf[4][2], wlf[4][2];
            #pragma unroll
            for (int mi = 0; mi < 4; mi++) {
                ldsm4(ahf[mi][0], ahf[mi][1], ahf[mi][2], ahf[mi][3],
                      aRow + stb + (u32)mi * 2048 + swA);
                ldsm4(alf[mi][0], alf[mi][1], alf[mi][2], alf[mi][3],
                      aRow + stb + 16384 + (u32)mi * 2048 + swA);
            }
            #pragma unroll
            for (int nj = 0; nj < 2; nj++) {
                u32 r0, r1, r2, r3;
                ldsm4(r0, r1, r2, r3, wRow + stb + 32768 + (u32)nj * 2048 + swW);
                whf[2 * nj][0] = r0; whf[2 * nj + 1][0] = r1;
                whf[2 * nj][1] = r2; whf[2 * nj + 1][1] = r3;
                ldsm4(r0, r1, r2, r3, wRow + stb + 49152 + (u32)nj * 2048 + swW);
                wlf[2 * nj][0] = r0; wlf[2 * nj + 1][0] = r1;
                wlf[2 * nj][1] = r2; wlf[2 * nj + 1][1] = r3;
            }
            #pragma unroll
            for (int mi = 0; mi < 4; mi++)
                #pragma unroll
                for (int n = 0; n < 4; n++) {
                    mma_bf16(acc[mi][n], ahf[mi], whf[n]);
                    mma_bf16(acc[mi][n], ahf[mi], wlf[n]);
                    mma_bf16(acc[mi][n], alf[mi], whf[n]);
                }
        }
        __syncthreads();
    }

    int er = lane >> 2, ec = (lane & 3) * 2;
    #pragma unroll
    for (int mi = 0; mi < 4; mi++) {
        int row0 = bm + wm + mi * 16 + er;
        #pragma unroll
        for (int n = 0; n < 4; n++) {
            int col = bn + wn + n * 8 + ec;
            float2 bv = *(const float2*)&bias[col];
            float2 v0 = make_float2(acc[mi][n][0] + bv.x, acc[mi][n][1] + bv.y);
            float2 v1 = make_float2(acc[mi][n][2] + bv.x, acc[mi][n][3] + bv.y);
            *(float2*)&C[(size_t)row0 * DIM + col]       = v0;
            *(float2*)&C[(size_t)(row0 + 8) * DIM + col] = v1;
        }
    }
}

// ---------------------------------------------------------------------------
// Tensor-core flash attention.
// CTA = (b,h) x 128 t-rows. 8 warps, warp owns 16 rows x full n-chunk (128).
// S = Q@K^T 3-term bf16 split; online softmax on C frags; P repacked to
// A frags (FA2 trick); P@V 3-term split with pre-transposed V.
// smem: Q(hi+lo) 32KB @0; 2 stages of [Kh 16K|Kl 16K|Vth 16K|Vtl 16K] @32768.
// ---------------------------------------------------------------------------
#define AT_SMEM (32768 + 2 * 65536)
__global__ __launch_bounds__(256, 1)
void attn_mma_kernel(const __nv_bfloat16* __restrict__ Qh, const __nv_bfloat16* __restrict__ Ql,
                     const __nv_bfloat16* __restrict__ Kh, const __nv_bfloat16* __restrict__ Kl,
                     const __nv_bfloat16* __restrict__ Vth, const __nv_bfloat16* __restrict__ Vtl,
                     __nv_bfloat16* __restrict__ OH, __nv_bfloat16* __restrict__ OL) {
    extern __shared__ char smem[];
    const u32 sb = smem_u32(smem);
    int tid = threadIdx.x;
    int wid = tid >> 5, lane = tid & 31;
    int bh = blockIdx.x;
    int b = bh >> 4, h = bh & 15;
    int t0 = blockIdx.y * 128;

    // global load mappings
    int lrow = tid >> 1, lhalf = tid & 1;   // Q/K: 128 rows x 128B
    int vrow = tid >> 2, vq = tid & 3;      // Vt: 64 rows x 256B
    const char* gqh = (const char*)(Qh + ((size_t)(b * TLEN + t0 + lrow)) * DIM + h * HDIM) + lhalf * 64;
    const char* gql = (const char*)(Ql + ((size_t)(b * TLEN + t0 + lrow)) * DIM + h * HDIM) + lhalf * 64;
    const char* gkh = (const char*)(Kh + ((size_t)(b * NLEN + lrow)) * DIM + h * HDIM) + lhalf * 64;
    const char* gkl = (const char*)(Kl + ((size_t)(b * NLEN + lrow)) * DIM + h * HDIM) + lhalf * 64;
    const char* gvh = (const char*)(Vth + ((size_t)(bh * HDIM + vrow)) * NLEN) + vq * 64;
    const char* gvl = (const char*)(Vtl + ((size_t)(bh * HDIM + vrow)) * NLEN) + vq * 64;

    auto issue_kv = [&](int stage, int c) {
        u32 st = sb + 32768 + (u32)stage * 65536;
        const char* pkh = gkh + (size_t)c * 262144;   // 128 rows * 2048 B
        const char* pkl = gkl + (size_t)c * 262144;
        const char* pvh = gvh + (size_t)c * 256;      // 128 bf16 cols
        const char* pvl = gvl + (size_t)c * 256;
        u32 kb = st + (u32)lrow * 128;
        u32 vb = st + 32768 + (u32)vrow * 256;
        #pragma unroll
        for (int j = 0; j < 4; j++) {
            u32 uk = (u32)(lhalf * 4 + j);
            u32 swk = (uk ^ (u32)(lrow & 7)) << 4;
            cpa(kb + swk, pkh + j * 16);
            cpa(kb + 16384 + swk, pkl + j * 16);
            u32 uv = (u32)(vq * 4 + j);
            u32 swv = (uv ^ (u32)(vrow & 7)) << 4;
            cpa(vb + swv, pvh + j * 16);
            cpa(vb + 16384 + swv, pvl + j * 16);
        }
        asm volatile("cp.async.commit_group;" ::: "memory");
    };

    // issue Q (group with chunk 0)
    {
        u32 qb = sb + (u32)lrow * 128;
        #pragma unroll
        for (int j = 0; j < 4; j++) {
            u32 u = (u32)(lhalf * 4 + j);
            u32 sw = (u ^ (u32)(lrow & 7)) << 4;
            cpa(qb + sw, gqh + j * 16);
            cpa(qb + 16384 + sw, gql + j * 16);
        }
    }
    issue_kv(0, 0);

    float so[8][4];
    #pragma unroll
    for (int f = 0; f < 8; f++)
        #pragma unroll
        for (int q = 0; q < 4; q++) so[f][q] = 0.f;
    float m0 = -INFINITY, m1 = -INFINITY, l0 = 0.f, l1 = 0.f;

    u32 qfh[4][4], qfl[4][4];
    u32 aRow = sb + (u32)(wid * 16 + (lane & 15)) * 128;
    int uu  = lane >> 4;
    int sw7 = lane & 7;

    for (int c = 0; c < 8; c++) {
        if (c + 1 < 8) {
            issue_kv((c + 1) & 1, c + 1);
            asm volatile("cp.async.wait_group 1;" ::: "memory");
        } else {
            asm volatile("cp.async.wait_group 0;" ::: "memory");
        }
        __syncthreads();

        if (c == 0) {
            #pragma unroll
            for (int ks = 0; ks < 4; ks++) {
                u32 sw = (u32)(((ks * 2 + uu) ^ sw7) << 4);
                ldsm4(qfh[ks][0], qfh[ks][1], qfh[ks][2], qfh[ks][3], aRow + sw);
                ldsm4(qfl[ks][0], qfl[ks][1], qfl[ks][2], qfl[ks][3], aRow + 16384 + sw);
            }
        }

        u32 st = sb + 32768 + (u32)(c & 1) * 65536;
        u32 kBase = st + (u32)(lane & 15) * 128;
        u32 vBase = st + 32768 + (u32)(lane & 15) * 256;

        // ---- S = Q @ K^T (3-term)
        float s[16][4];
        #pragma unroll
        for (int f = 0; f < 16; f++)
            #pragma unroll
            for (int q = 0; q < 4; q++) s[f][q] = 0.f;
        #pragma unroll
        for (int ks = 0; ks < 4; ks++) {
            u32 sw = (u32)(((ks * 2 + uu) ^ sw7) << 4);
            #pragma unroll
            for (int nj = 0; nj < 8; nj++) {
                u32 ka = kBase + (u32)nj * 2048 + sw;
                u32 h0, h1, h2, h3, e0, e1, e2, e3;
                ldsm4(h0, h1, h2, h3, ka);
                ldsm4(e0, e1, e2, e3, ka + 16384);
                u32 bh0[2] = {h0, h2}, bh1[2] = {h1, h3};
                u32 bl0[2] = {e0, e2}, bl1[2] = {e1, e3};
                mma_bf16(s[2 * nj],     qfh[ks], bh0);
                mma_bf16(s[2 * nj],     qfh[ks], bl0);
                mma_bf16(s[2 * nj],     qfl[ks], bh0);
                mma_bf16(s[2 * nj + 1], qfh[ks], bh1);
                mma_bf16(s[2 * nj + 1], qfh[ks], bl1);
                mma_bf16(s[2 * nj + 1], qfl[ks], bh1);
            }
        }

        // ---- online softmax
        float mx0 = -INFINITY, mx1 = -INFINITY;
        #pragma unroll
        for (int f = 0; f < 16; f++) {
            mx0 = fmaxf(mx0, fmaxf(s[f][0], s[f][1]));
            mx1 = fmaxf(mx1, fmaxf(s[f][2], s[f][3]));
        }
        mx0 = fmaxf(mx0, __shfl_xor_sync(0xffffffffu, mx0, 1));
        mx0 = fmaxf(mx0, __shfl_xor_sync(0xffffffffu, mx0, 2));
        mx1 = fmaxf(mx1, __shfl_xor_sync(0xffffffffu, mx1, 1));
        mx1 = fmaxf(mx1, __shfl_xor_sync(0xffffffffu, mx1, 2));
        float mn0 = fmaxf(m0, mx0), mn1 = fmaxf(m1, mx1);
        float sc0 = __expf(m0 - mn0), sc1 = __expf(m1 - mn1);
        m0 = mn0; m1 = mn1;
        float rs0 = 0.f, rs1 = 0.f;
        #pragma unroll
        for (int f = 0; f < 16; f++) {
            s[f][0] = __expf(s[f][0] - mn0); rs0 += s[f][0];
            s[f][1] = __expf(s[f][1] - mn0); rs0 += s[f][1];
            s[f][2] = __expf(s[f][2] - mn1); rs1 += s[f][2];
            s[f][3] = __expf(s[f][3] - mn1); rs1 += s[f][3];
        }
        rs0 += __shfl_xor_sync(0xffffffffu, rs0, 1);
        rs0 += __shfl_xor_sync(0xffffffffu, rs0, 2);
        rs1 += __shfl_xor_sync(0xffffffffu, rs1, 1);
        rs1 += __shfl_xor_sync(0xffffffffu, rs1, 2);
        l0 = l0 * sc0 + rs0;
        l1 = l1 * sc1 + rs1;
        #pragma unroll
        for (int f = 0; f < 8; f++) {
            so[f][0] *= sc0; so[f][1] *= sc0;
            so[f][2] *= sc1; so[f][3] *= sc1;
        }

        // ---- O += P @ V (3-term), P frags from S frags
        #pragma unroll
        for (int j = 0; j < 8; j++) {
            u32 phi[4], plo[4];
            phi[0] = pack_bf16(s[2 * j][0], s[2 * j][1]);
            phi[1] = pack_bf16(s[2 * j][2], s[2 * j][3]);
            phi[2] = pack_bf16(s[2 * j + 1][0], s[2 * j + 1][1]);
            phi[3] = pack_bf16(s[2 * j + 1][2], s[2 * j + 1][3]);
            plo[0] = pack_resid(phi[0], s[2 * j][0], s[2 * j][1]);
            plo[1] = pack_resid(phi[1], s[2 * j][2], s[2 * j][3]);
            plo[2] = pack_resid(phi[2], s[2 * j + 1][0], s[2 * j + 1][1]);
            plo[3] = pack_resid(phi[3], s[2 * j + 1][2], s[2 * j + 1][3]);
            u32 swv = (u32)(((j * 2 + uu) ^ sw7) << 4);
            #pragma unroll
            for (int dj = 0; dj < 4; dj++) {
                u32 va = vBase + (u32)dj * 4096 + swv;
                u32 h0, h1, h2, h3, e0, e1, e2, e3;
                ldsm4(h0, h1, h2, h3, va);
                ldsm4(e0, e1, e2, e3, va + 16384);
                u32 bh0[2] = {h0, h2}, bh1[2] = {h1, h3};
                u32 bl0[2] = {e0, e2}, bl1[2] = {e1, e3};
                mma_bf16(so[2 * dj],     phi, bh0);
                mma_bf16(so[2 * dj],     phi, bl0);
                mma_bf16(so[2 * dj],     plo, bh0);
                mma_bf16(so[2 * dj + 1], phi, bh1);
                mma_bf16(so[2 * dj + 1], phi, bl1);
                mma_bf16(so[2 * dj + 1], plo, bh1);
            }
        }
        __syncthreads();
    }

    // ---- epilogue: normalize, bf16 hi/lo split -> OH/OL
    float inv0 = 1.f / l0, inv1 = 1.f / l1;
    int r0g = b * TLEN + t0 + wid * 16 + (lane >> 2);
    int colb = h * HDIM + 2 * (lane & 3);
    #pragma unroll
    for (int f = 0; f < 8; f++) {
        float f0 = so[f][0] * inv0, f1 = so[f][1] * inv0;
        float f2 = so[f][2] * inv1, f3 = so[f][3] * inv1;
        int col = colb + f * 8;
        size_t i0 = (size_t)r0g * DIM + col;
        size_t i1 = (size_t)(r0g + 8) * DIM + col;
        u32 hp0 = pack_bf16(f0, f1);
        u32 hp1 = pack_bf16(f2, f3);
        *(u32*)(OH + i0) = hp0;
        *(u32*)(OH + i1) = hp1;
        *(u32*)(OL + i0) = pack_resid(hp0, f0, f1);
        *(u32*)(OL + i1) = pack_resid(hp1, f2, f3);
    }
}

// ---------------------------------------------------------------------------
extern "C" void kernel_launch(void* const* d_in, const int* in_sizes, int n_in,
                              void* d_out, int out_size) {
    const float* text     = (const float*)d_in[0];
    const float* features = (const float*)d_in[1];
    const float* W_q      = (const float*)d_in[2];
    const float* b_q      = (const float*)d_in[3];
    const float* W_k      = (const float*)d_in[4];
    const float* b_k      = (const float*)d_in[5];
    const float* W_o      = (const float*)d_in[6];
    const float* b_o      = (const float*)d_in[7];
    const float* g_feat   = (const float*)d_in[8];
    const float* g_q      = (const float*)d_in[9];
    const float* g_k      = (const float*)d_in[10];
    float* out = (float*)d_out;

    float *Qb, *Kb;
    cudaGetSymbolAddress((void**)&Qb, g_Qbuf);
    cudaGetSymbolAddress((void**)&Kb, g_Kbuf);

    __nv_bfloat16 *th, *tl, *fh, *fl, *ah, *al, *qh, *ql, *kh, *kl, *vth, *vtl;
    __nv_bfloat16 *wqh, *wql, *wkh, *wkl, *woh, *wol;
    cudaGetSymbolAddress((void**)&th,  g_th);
    cudaGetSymbolAddress((void**)&tl,  g_tl);
    cudaGetSymbolAddress((void**)&fh,  g_fh);
    cudaGetSymbolAddress((void**)&fl,  g_fl);
    cudaGetSymbolAddress((void**)&ah,  g_ah);
    cudaGetSymbolAddress((void**)&al,  g_al);
    cudaGetSymbolAddress((void**)&qh,  g_qh);
    cudaGetSymbolAddress((void**)&ql,  g_ql);
    cudaGetSymbolAddress((void**)&kh,  g_kh);
    cudaGetSymbolAddress((void**)&kl,  g_kl);
    cudaGetSymbolAddress((void**)&vth, g_vth);
    cudaGetSymbolAddress((void**)&vtl, g_vtl);
    cudaGetSymbolAddress((void**)&wqh, g_wqh);
    cudaGetSymbolAddress((void**)&wql, g_wql);
    cudaGetSymbolAddress((void**)&wkh, g_wkh);
    cudaGetSymbolAddress((void**)&wkl, g_wkl);
    cudaGetSymbolAddress((void**)&woh, g_woh);
    cudaGetSymbolAddress((void**)&wol, g_wol);

    static int attrs_set = 0;
    if (!attrs_set) {
        cudaFuncSetAttribute(mma_gemm_kernel,
                             cudaFuncAttributeMaxDynamicSharedMemorySize, MM_SMEM);
        cudaFuncSetAttribute(attn_mma_kernel,
                             cudaFuncAttributeMaxDynamicSharedMemorySize, AT_SMEM);
        attrs_set = 1;
    }

    const int MT = BATCH * TLEN;   // 4096
    const int MN = BATCH * NLEN;   // 8192

    // 1. feats = rmsnorm(features) -> bf16 splits (V and K-GEMM input)
    rmsnorm_split_kernel<<<MN, 256>>>(features, g_feat, 1.0f, fh, fl);

    // 2. V^T per head
    transpose_vt_kernel<<<dim3(NLEN / 32, HDIM / 32, BATCH * HEADS), dim3(32, 8)>>>(fh, fl, vth, vtl);

    // 3. bf16 splits of text + weights
    convert_split_kernel<<<(MT * DIM / 4) / 256, 256>>>(text, th, tl);
    convert_split_kernel<<<(DIM * DIM / 4) / 256, 256>>>(W_q, wqh, wql);
    convert_split_kernel<<<(DIM * DIM / 4) / 256, 256>>>(W_k, wkh, wkl);
    convert_split_kernel<<<(DIM * DIM / 4) / 256, 256>>>(W_o, woh, wol);

    // 4. Q = rmsnorm(text @ Wq^T + bq) -> scaled bf16 splits (x 1/8)
    mma_gemm_kernel<<<dim3(8, MT / 128), 256, MM_SMEM>>>(th, tl, wqh, wql, b_q, Qb);
    rmsnorm_split_kernel<<<MT, 256>>>(Qb, g_q, 0.125f, qh, ql);

    // 5. K = rmsnorm(feats @ Wk^T + bk) -> bf16 splits
    mma_gemm_kernel<<<dim3(8, MN / 128), 256, MM_SMEM>>>(fh, fl, wkh, wkl, b_k, Kb);
    rmsnorm_split_kernel<<<MN, 256>>>(Kb, g_k, 1.0f, kh, kl);

    // 6. attention (tensor cores) -> bf16 splits of attn output
    attn_mma_kernel<<<dim3(BATCH * HEADS, TLEN / 128), 256, AT_SMEM>>>(
        qh, ql, kh, kl, vth, vtl, ah, al);

    // 7. out = attnOut @ Wo^T + bo
    mma_gemm_kernel<<<dim3(8, MT / 128), 256, MM_SMEM>>>(ah, al, woh, wol, b_o, out);
}